// round 9
// baseline (speedup 1.0000x reference)
#include <cuda_runtime.h>
#include <cuda_bf16.h>
#include <cstdint>

// Problem constants (fixed by setup_inputs)
#define CB 8
#define CH 96
#define CW 96
#define CC 192
#define CT (CH*CW)          // 9216
#define CM (CB*CT)          // 73728
#define L2E 1.4426950408889634f
#define NCHUNK 192
#define CS 48               // wkv chunk size

// ---------------- scratch (static __device__; no runtime allocation) -------
__device__ __align__(16) float    g_cw[25*CC];      // combined 5x5 dw weights [tap][C]
__device__ __align__(16) uint16_t g_xh[CM*CC];      // omni-shift output, bf16 hi
__device__ __align__(16) uint16_t g_xl[CM*CC];      // bf16 lo residual
__device__ __align__(16) float    g_k [CM*CC];
__device__ __align__(16) float    g_v [CM*CC];      // v -> y1 (in-place for scan 0)
__device__ __align__(16) float    g_r [CM*CC];      // sigmoid(r)
__device__ __align__(16) uint16_t g_rvh[CM*CC];     // sigmoid(r)*y2, bf16 hi
__device__ __align__(16) uint16_t g_rvl[CM*CC];     // bf16 lo
__device__ __align__(16) uint16_t g_wh[4*CC*CC];    // [Wk|Wv|Wr|Wo] bf16 hi
__device__ __align__(16) uint16_t g_wl[4*CC*CC];    // bf16 lo
__device__ __align__(16) float    g_sp[CB*NCHUNK*CC];
__device__ __align__(16) float    g_sq[CB*NCHUNK*CC];
__device__ __align__(16) float    g_so[CB*NCHUNK*CC];

// ---------------- helpers --------------------------------------------------
__device__ __forceinline__ uint32_t smem_u32(const void* p) {
    uint32_t a;
    asm("{ .reg .u64 t; cvta.to.shared.u64 t, %1; cvt.u32.u64 %0, t; }" : "=r"(a) : "l"(p));
    return a;
}
__device__ __forceinline__ void split1(float a, uint16_t& hi, uint16_t& lo) {
    __nv_bfloat16 h = __float2bfloat16(a);
    float res = a - __bfloat162float(h);
    hi = __bfloat16_as_ushort(h);
    lo = __bfloat16_as_ushort(__float2bfloat16(res));
}
__device__ __forceinline__ void cp16(uint32_t sdst, const void* gsrc) {
    uint64_t ga; asm("cvta.to.global.u64 %0, %1;" : "=l"(ga) : "l"(gsrc));
    asm volatile("cp.async.ca.shared.global [%0], [%1], 16;" :: "r"(sdst), "l"(ga));
}
__device__ __forceinline__ void ldsm4(uint32_t* r, uint32_t addr) {
    asm volatile("ldmatrix.sync.aligned.m8n8.x4.shared.b16 {%0,%1,%2,%3}, [%4];"
        : "=r"(r[0]), "=r"(r[1]), "=r"(r[2]), "=r"(r[3]) : "r"(addr));
}
__device__ __forceinline__ void mma_bf16(float* c, const uint32_t* a, uint32_t b0, uint32_t b1) {
    asm volatile("mma.sync.aligned.m16n8k16.row.col.f32.bf16.bf16.f32 "
        "{%0,%1,%2,%3}, {%4,%5,%6,%7}, {%8,%9}, {%0,%1,%2,%3};"
        : "+f"(c[0]), "+f"(c[1]), "+f"(c[2]), "+f"(c[3])
        : "r"(a[0]), "r"(a[1]), "r"(a[2]), "r"(a[3]), "r"(b0), "r"(b1));
}

// ---------------- 1. combine omni-shift weights ---------------------------
__global__ void combine_cw(const float* __restrict__ alpha,
                           const float* __restrict__ w1,
                           const float* __restrict__ w3,
                           const float* __restrict__ w5) {
    int idx = blockIdx.x * blockDim.x + threadIdx.x;
    if (idx >= CC*25) return;
    int c = idx / 25, tap = idx % 25;
    int dy = tap / 5, dx = tap % 5;
    float v = alpha[3] * w5[c*25 + tap];
    if (dy == 2 && dx == 2) v += alpha[0] + alpha[1] * w1[c];
    if (dy >= 1 && dy <= 3 && dx >= 1 && dx <= 3)
        v += alpha[2] * w3[c*9 + (dy-1)*3 + (dx-1)];
    g_cw[tap*CC + c] = v;
}

// ---------------- 1b. split projection weights to bf16 hi/lo ---------------
__global__ void prep_w(const float* __restrict__ Wk, const float* __restrict__ Wv,
                       const float* __restrict__ Wr, const float* __restrict__ Wo) {
    int i = blockIdx.x * blockDim.x + threadIdx.x;
    if (i >= 4*CC*CC) return;
    int widx = i / (CC*CC), off = i % (CC*CC);
    const float* W = (widx == 0) ? Wk : (widx == 1) ? Wv : (widx == 2) ? Wr : Wo;
    split1(W[off], g_wh[i], g_wl[i]);
}

// ---------------- 2. depthwise 5x5 conv (writes bf16 hi/lo) ----------------
__global__ __launch_bounds__(CC) void conv5(const float* __restrict__ x) {
    int h = blockIdx.x, b = blockIdx.y, c = threadIdx.x;
    float wr[25];
#pragma unroll
    for (int t = 0; t < 25; t++) wr[t] = g_cw[t*CC + c];
    bool rv[5];
#pragma unroll
    for (int dy = 0; dy < 5; dy++) rv[dy] = (unsigned)(h - 2 + dy) < CH;
    const float* xb = x + (size_t)b*CT*CC + c;
    uint16_t* oh = g_xh + (size_t)b*CT*CC + c;
    uint16_t* ol = g_xl + (size_t)b*CT*CC + c;
    float win[5][5];
#pragma unroll
    for (int dy = 0; dy < 5; dy++) {
        int hy = h - 2 + dy;
        win[dy][0] = 0.f; win[dy][1] = 0.f;
        win[dy][2] = rv[dy] ? xb[(size_t)(hy*CW + 0)*CC] : 0.f;
        win[dy][3] = rv[dy] ? xb[(size_t)(hy*CW + 1)*CC] : 0.f;
        win[dy][4] = 0.f;
    }
#pragma unroll 4
    for (int w = 0; w < CW; w++) {
        int wx = w + 2;
        bool cv = wx < CW;
#pragma unroll
        for (int dy = 0; dy < 5; dy++)
            win[dy][4] = (rv[dy] && cv) ? xb[(size_t)((h-2+dy)*CW + wx)*CC] : 0.f;
        float acc = 0.f;
#pragma unroll
        for (int dy = 0; dy < 5; dy++)
#pragma unroll
            for (int j = 0; j < 5; j++)
                acc = fmaf(win[dy][j], wr[dy*5+j], acc);
        uint16_t hi, lo; split1(acc, hi, lo);
        oh[(size_t)(h*CW + w)*CC] = hi;
        ol[(size_t)(h*CW + w)*CC] = lo;
#pragma unroll
        for (int dy = 0; dy < 5; dy++)
#pragma unroll
            for (int j = 0; j < 4; j++)
                win[dy][j] = win[dy][j+1];
    }
}

// ================= HMMA bf16 GEMM, 512 thr, CTA 128x192, 2-stage cp.async ==
// C[m,n] = sum_k A[m,k]*W[n,k]; 3-pass split: Ah*Bh + Ah*Bl + Al*Bh.
// Warp layout 4m x 4n, warp tile 32x48, BK=32.
// Stage layout (bytes): Ah[0,10240) Al[10240,20480) Bh[20480,35840) Bl[35840,51200)
#define STG_BYTES 51200
#define SMEM_TOTAL (2*STG_BYTES)

__device__ __forceinline__ void issue_stage(uint32_t sb_st,
        const uint16_t* Agh, const uint16_t* Agl,
        const uint16_t* Bgh, const uint16_t* Bgl, int mb, int k0) {
    int tid = threadIdx.x;
#pragma unroll
    for (int it = 0; it < 5; it++) {
        int id = tid + it*512;
        if (id < 1024) {
            int arr = id >> 9, i2 = id & 511;
            int row = i2 >> 2, koff = i2 & 3;
            const uint16_t* g = (arr ? Agl : Agh) + (size_t)(mb + row)*CC + k0 + koff*8;
            cp16(sb_st + arr*10240 + row*80 + koff*16, g);
        } else {
            int id2 = id - 1024;
            int arr = (id2 >= 768) ? 1 : 0;
            int i3 = id2 - arr*768;
            int row = i3 >> 2, koff = i3 & 3;
            const uint16_t* g = (arr ? Bgl : Bgh) + (size_t)row*CC + k0 + koff*8;
            cp16(sb_st + 20480 + arr*15360 + row*80 + koff*16, g);
        }
    }
    asm volatile("cp.async.commit_group;" ::: "memory");
}

__device__ __forceinline__ void gemm_core(const uint16_t* Agh, const uint16_t* Agl,
        const uint16_t* Bgh, const uint16_t* Bgl,
        float* Out, int mb, bool dosig) {
    extern __shared__ __align__(16) uint16_t smraw[];
    uint32_t sb = smem_u32(smraw);
    int tid = threadIdx.x, lane = tid & 31, wid = tid >> 5;
    int warp_m = (wid & 3) * 32, warp_n = (wid >> 2) * 48;

    float acc[2][6][4];
#pragma unroll
    for (int i = 0; i < 2; i++)
#pragma unroll
        for (int j = 0; j < 6; j++)
#pragma unroll
            for (int q = 0; q < 4; q++) acc[i][j][q] = 0.f;

    issue_stage(sb, Agh, Agl, Bgh, Bgl, mb, 0);

#pragma unroll 1
    for (int st = 0; st < 6; st++) {
        if (st < 5) {
            issue_stage(sb + ((st+1)&1)*STG_BYTES, Agh, Agl, Bgh, Bgl, mb, (st+1)*32);
            asm volatile("cp.async.wait_group 1;" ::: "memory");
        } else {
            asm volatile("cp.async.wait_group 0;" ::: "memory");
        }
        __syncthreads();
        uint32_t base = sb + (st&1)*STG_BYTES;
        uint32_t ah_b = base, al_b = base + 10240;
        uint32_t bh_b = base + 20480, bl_b = base + 35840;
#pragma unroll 1
        for (int ks = 0; ks < 2; ks++) {
            int arow = warp_m + (lane & 15);
            int acol = ks*16 + (lane >> 4)*8;
            uint32_t ahf[2][4], alf[2][4];
#pragma unroll
            for (int mt = 0; mt < 2; mt++) {
                uint32_t bo = (uint32_t)((arow + mt*16)*80 + acol*2);
                ldsm4(ahf[mt], ah_b + bo);
                ldsm4(alf[mt], al_b + bo);
            }
            int brow = warp_n + (lane & 7) + ((lane >> 4) << 3);
            int bcol = ks*16 + (((lane >> 3) & 1) << 3);
#pragma unroll
            for (int np = 0; np < 3; np++) {
                uint32_t bhf[4], blf[4];
                uint32_t bo = (uint32_t)((brow + np*16)*80 + bcol*2);
                ldsm4(bhf, bh_b + bo);
                ldsm4(blf, bl_b + bo);
#pragma unroll
                for (int half = 0; half < 2; half++) {
                    int nt = np*2 + half;
#pragma unroll
                    for (int mt = 0; mt < 2; mt++) {
                        mma_bf16(acc[mt][nt], ahf[mt], bhf[half*2], bhf[half*2+1]);
                        mma_bf16(acc[mt][nt], ahf[mt], blf[half*2], blf[half*2+1]);
                        mma_bf16(acc[mt][nt], alf[mt], bhf[half*2], bhf[half*2+1]);
                    }
                }
            }
        }
        __syncthreads();
    }

    int g = lane >> 2, tig = lane & 3;
#pragma unroll
    for (int mt = 0; mt < 2; mt++) {
#pragma unroll
        for (int nt = 0; nt < 6; nt++) {
            int m0 = mb + warp_m + mt*16 + g;
            int col = warp_n + nt*8 + tig*2;
            float2 v0 = make_float2(acc[mt][nt][0], acc[mt][nt][1]);
            float2 v1 = make_float2(acc[mt][nt][2], acc[mt][nt][3]);
            if (dosig) {
                v0.x = 1.f/(1.f+__expf(-v0.x)); v0.y = 1.f/(1.f+__expf(-v0.y));
                v1.x = 1.f/(1.f+__expf(-v1.x)); v1.y = 1.f/(1.f+__expf(-v1.y));
            }
            *(float2*)&Out[(size_t)m0*CC + col]     = v0;
            *(float2*)&Out[(size_t)(m0+8)*CC + col] = v1;
        }
    }
}

__global__ __launch_bounds__(512)
void gemm_kvr_h() {
    int sel = blockIdx.x;
    const uint16_t* Bh = g_wh + (size_t)sel*CC*CC;
    const uint16_t* Bl = g_wl + (size_t)sel*CC*CC;
    float* Out = (sel == 0) ? g_k : (sel == 1) ? g_v : g_r;
    gemm_core(g_xh, g_xl, Bh, Bl, Out, blockIdx.y * 128, sel == 2);
}

__global__ __launch_bounds__(512)
void gemm_out_h(float* __restrict__ outp) {
    gemm_core(g_rvh, g_rvl, g_wh + (size_t)3*CC*CC, g_wl + (size_t)3*CC*CC,
              outp, blockIdx.y * 128, false);
}

// ---------------- 4. WKV chunked parallel scan (chunk = 48) ----------------
__device__ __forceinline__ void chunk_map(int ci, int j, int& t0, int& stp) {
    if (j == 0) { t0 = ci * CS; stp = 1; }
    else        { t0 = ((ci & 1) * CS) * CW + (ci >> 1); stp = CW; }
}

__global__ void wkv_pass1(const float* __restrict__ sd, int j) {
    int ci = blockIdx.x, b = blockIdx.y, c = threadIdx.x;
    float w  = sd[c] * (1.0f/(float)CT);
    float wl = w * L2E;
    float S = 0.f, Sq = 0.f, off = -wl;
    size_t base = (size_t)b*CT*CC + c;
    int t0, stp; chunk_map(ci, j, t0, stp);
    size_t o = base + (size_t)t0*CC;
    size_t ostep = (size_t)stp*CC;
    float kc = g_k[o], vc = g_v[o];
#pragma unroll 4
    for (int i = 0; i < CS; i++) {
        o += ostep;
        float kn = 0.f, vn = 0.f;
        if (i < CS-1) { kn = g_k[o]; vn = g_v[o]; }
        float E = exp2f(fmaf(kc, L2E, off));
        S  = fmaf(E, vc, S);
        Sq += E;
        off -= wl;
        kc = kn; vc = vn;
    }
    int sidx = (b*NCHUNK + ci)*CC + c;
    g_sp[sidx] = S; g_sq[sidx] = Sq;
}

__global__ void wkv_cscan(const float* __restrict__ sd) {
    int b = blockIdx.x, c = threadIdx.x;
    float w  = sd[c] * (1.0f/(float)CT);
    float Wc = (float)CS * w;
    float p = 0.f, q = 0.f, o = -1e38f;
    for (int ci = 0; ci < NCHUNK; ci++) {
        int sidx = (b*NCHUNK + ci)*CC + c;
        float Pc = g_sp[sidx], Qc = g_sq[sidx];
        g_sp[sidx] = p; g_sq[sidx] = q; g_so[sidx] = o;
        float o1 = o + Wc;
        float no = fmaxf(o1, Wc);
        float e1 = exp2f((o1 - no)*L2E);
        float e2 = exp2f((Wc - no)*L2E);
        p = fmaf(e1, p, e2*Pc);
        q = fmaf(e1, q, e2*Qc);
        o = no;
    }
}

// fuse=0: write y to g_v (scan 0). fuse=1: write bf16 split of sigmoid_r*y (scan 1).
__global__ void wkv_pass2(const float* __restrict__ sd, const float* __restrict__ sf,
                          int j, int fuse) {
    int ci = blockIdx.x, b = blockIdx.y, c = threadIdx.x;
    float w  = sd[c] * (1.0f/(float)CT);
    float u  = sf[c] * (1.0f/(float)CT);
    float wl = w * L2E;
    float c1 = exp2f(-(u + w)*L2E);
    int sidx = (b*NCHUNK + ci)*CC + c;
    float p = g_sp[sidx], q = g_sq[sidx], o = g_so[sidx];
    float offu;
    if (o < -1e30f) { p = 0.f; q = 0.f; offu = u*L2E; }
    else            { offu = (u - o)*L2E; }
    size_t base = (size_t)b*CT*CC + c;
    int t0, stp; chunk_map(ci, j, t0, stp);
    size_t oc = base + (size_t)t0*CC;
    size_t ostep = (size_t)stp*CC;
    float kc = g_k[oc], vc = g_v[oc];
#pragma unroll 4
    for (int i = 0; i < CS; i++) {
        size_t on = oc + ostep;
        float kn = 0.f, vn = 0.f;
        if (i < CS-1) { kn = g_k[on]; vn = g_v[on]; }
        float Eu = exp2f(fmaf(kc, L2E, offu));
        float y  = __fdividef(fmaf(Eu, vc, p), q + Eu);
        if (fuse) {
            float rvv = g_r[oc] * y;
            split1(rvv, g_rvh[oc], g_rvl[oc]);
        } else {
            g_v[oc] = y;
        }
        float E = Eu * c1;
        p = fmaf(E, vc, p);
        q += E;
        offu -= wl;
        oc = on; kc = kn; vc = vn;
    }
}

// ---------------- launcher -------------------------------------------------
extern "C" void kernel_launch(void* const* d_in, const int* in_sizes, int n_in,
                              void* d_out, int out_size) {
    const float* x     = (const float*)d_in[0];
    const float* alpha = (const float*)d_in[1];
    const float* w1    = (const float*)d_in[2];
    const float* w3    = (const float*)d_in[3];
    const float* w5    = (const float*)d_in[4];
    const float* Wk    = (const float*)d_in[5];
    const float* Wv    = (const float*)d_in[6];
    const float* Wr    = (const float*)d_in[7];
    const float* Wo    = (const float*)d_in[8];
    const float* sd    = (const float*)d_in[9];
    const float* sf    = (const float*)d_in[10];
    float* out = (float*)d_out;

    static int attr_done = 0;
    if (!attr_done) {
        cudaFuncSetAttribute(gemm_kvr_h, cudaFuncAttributeMaxDynamicSharedMemorySize, SMEM_TOTAL);
        cudaFuncSetAttribute(gemm_out_h, cudaFuncAttributeMaxDynamicSharedMemorySize, SMEM_TOTAL);
        attr_done = 1;
    }

    combine_cw<<<(CC*25 + 255)/256, 256>>>(alpha, w1, w3, w5);
    prep_w<<<(4*CC*CC + 255)/256, 256>>>(Wk, Wv, Wr, Wo);
    conv5<<<dim3(CH, CB), CC>>>(x);
    gemm_kvr_h<<<dim3(3, CM/128), 512, SMEM_TOTAL>>>();

    // scan j = 0: row-major
    wkv_pass1<<<dim3(NCHUNK, CB), CC>>>(sd, 0);
    wkv_cscan<<<CB, CC>>>(sd);
    wkv_pass2<<<dim3(NCHUNK, CB), CC>>>(sd, sf, 0, 0);

    // scan j = 1: column-major (fused sigmoid_r*y split epilogue)
    wkv_pass1<<<dim3(NCHUNK, CB), CC>>>(sd + CC, 1);
    wkv_cscan<<<CB, CC>>>(sd + CC);
    wkv_pass2<<<dim3(NCHUNK, CB), CC>>>(sd + CC, sf + CC, 1, 1);

    gemm_out_h<<<dim3(1, CM/128), 512, SMEM_TOTAL>>>(out);
}

// round 10
// speedup vs baseline: 1.2363x; 1.2363x over previous
#include <cuda_runtime.h>
#include <cuda_bf16.h>
#include <cstdint>

// Problem constants (fixed by setup_inputs)
#define CB 8
#define CH 96
#define CW 96
#define CC 192
#define CT (CH*CW)          // 9216
#define CM (CB*CT)          // 73728
#define L2E 1.4426950408889634f
#define NCHUNK 192
#define CS 48               // wkv chunk size

// ---------------- scratch (static __device__; no runtime allocation) -------
__device__ __align__(16) float g_cw[25*CC];     // combined 5x5 dw weights [tap][C]
__device__ __align__(16) float g_xs[CM*CC];     // omni-shift output
__device__ __align__(16) float g_k [CM*CC];
__device__ __align__(16) float g_v [CM*CC];     // v -> y1 -> y2 (in-place)
__device__ __align__(16) float g_r [CM*CC];     // sigmoid(r)
__device__ __align__(16) float g_sp[CB*NCHUNK*CC];
__device__ __align__(16) float g_sq[CB*NCHUNK*CC];
__device__ __align__(16) float g_so[CB*NCHUNK*CC];

// ---------------- 1. combine omni-shift weights ---------------------------
__global__ void combine_cw(const float* __restrict__ alpha,
                           const float* __restrict__ w1,
                           const float* __restrict__ w3,
                           const float* __restrict__ w5) {
    int idx = blockIdx.x * blockDim.x + threadIdx.x;
    if (idx >= CC*25) return;
    int c = idx / 25, tap = idx % 25;
    int dy = tap / 5, dx = tap % 5;
    float v = alpha[3] * w5[c*25 + tap];
    if (dy == 2 && dx == 2) v += alpha[0] + alpha[1] * w1[c];
    if (dy >= 1 && dy <= 3 && dx >= 1 && dx <= 3)
        v += alpha[2] * w3[c*9 + (dy-1)*3 + (dx-1)];
    g_cw[tap*CC + c] = v;
}

// ---------------- 2. depthwise 5x5 conv: 2 output rows per block -----------
// grid (CH/2, CB), 192 threads; 6-row register sliding window.
__global__ __launch_bounds__(CC) void conv5(const float* __restrict__ x) {
    int h0 = blockIdx.x * 2, b = blockIdx.y, c = threadIdx.x;
    float wr[25];
#pragma unroll
    for (int t = 0; t < 25; t++) wr[t] = g_cw[t*CC + c];
    bool rv[6];
#pragma unroll
    for (int r = 0; r < 6; r++) rv[r] = (unsigned)(h0 - 2 + r) < CH;
    const float* xb = x    + (size_t)b*CT*CC + c;
    float*       ob = g_xs + (size_t)b*CT*CC + c;
    float win[6][5];
#pragma unroll
    for (int r = 0; r < 6; r++) {
        int hy = h0 - 2 + r;
        win[r][0] = 0.f; win[r][1] = 0.f;
        win[r][2] = rv[r] ? xb[(size_t)(hy*CW + 0)*CC] : 0.f;
        win[r][3] = rv[r] ? xb[(size_t)(hy*CW + 1)*CC] : 0.f;
        win[r][4] = 0.f;
    }
#pragma unroll 4
    for (int w = 0; w < CW; w++) {
        int wx = w + 2;
        bool cv = wx < CW;
#pragma unroll
        for (int r = 0; r < 6; r++)
            win[r][4] = (rv[r] && cv) ? xb[(size_t)((h0-2+r)*CW + wx)*CC] : 0.f;
        float a0 = 0.f, a1 = 0.f;
#pragma unroll
        for (int dy = 0; dy < 5; dy++)
#pragma unroll
            for (int j = 0; j < 5; j++) {
                a0 = fmaf(win[dy][j],   wr[dy*5+j], a0);
                a1 = fmaf(win[dy+1][j], wr[dy*5+j], a1);
            }
        ob[(size_t)(h0*CW + w)*CC]     = a0;
        ob[(size_t)((h0+1)*CW + w)*CC] = a1;
#pragma unroll
        for (int r = 0; r < 6; r++)
#pragma unroll
            for (int j = 0; j < 4; j++)
                win[r][j] = win[r][j+1];
    }
}

// ================= HMMA bf16 GEMM (R5 561us version, verbatim) =============
#define GSTRIDE 40   // smem row stride in bf16 elements (80 bytes)

__device__ __forceinline__ void split2(float a, float b, uint32_t& hi, uint32_t& lo) {
    __nv_bfloat16 ha = __float2bfloat16(a), hb = __float2bfloat16(b);
    float ra = a - __bfloat162float(ha), rb = b - __bfloat162float(hb);
    __nv_bfloat16 la = __float2bfloat16(ra), lb = __float2bfloat16(rb);
    hi = ((uint32_t)__bfloat16_as_ushort(hb) << 16) | (uint32_t)__bfloat16_as_ushort(ha);
    lo = ((uint32_t)__bfloat16_as_ushort(lb) << 16) | (uint32_t)__bfloat16_as_ushort(la);
}
__device__ __forceinline__ uint32_t smem_u32(const void* p) {
    uint32_t a;
    asm("{ .reg .u64 t; cvta.to.shared.u64 t, %1; cvt.u32.u64 %0, t; }" : "=r"(a) : "l"(p));
    return a;
}
__device__ __forceinline__ void ldsm4(uint32_t* r, uint32_t addr) {
    asm volatile("ldmatrix.sync.aligned.m8n8.x4.shared.b16 {%0,%1,%2,%3}, [%4];"
        : "=r"(r[0]), "=r"(r[1]), "=r"(r[2]), "=r"(r[3]) : "r"(addr));
}
__device__ __forceinline__ void mma_bf16(float* c, const uint32_t* a, uint32_t b0, uint32_t b1) {
    asm volatile("mma.sync.aligned.m16n8k16.row.col.f32.bf16.bf16.f32 "
        "{%0,%1,%2,%3}, {%4,%5,%6,%7}, {%8,%9}, {%0,%1,%2,%3};"
        : "+f"(c[0]), "+f"(c[1]), "+f"(c[2]), "+f"(c[3])
        : "r"(a[0]), "r"(a[1]), "r"(a[2]), "r"(a[3]), "r"(b0), "r"(b1));
}

struct GemmSmem {
    uint16_t Ah[128*GSTRIDE];
    uint16_t Al[128*GSTRIDE];
    uint16_t Bh[96*GSTRIDE];
    uint16_t Bl[96*GSTRIDE];
};

__device__ __forceinline__ void gemm_core(bool is_out, const float* __restrict__ Wsrc,
                                          float* __restrict__ Out, int nloc, int mb,
                                          bool dosig, GemmSmem& S) {
    int tid = threadIdx.x, lane = tid & 31, wid = tid >> 5;
    int warp_m = (wid & 3) * 32, warp_n = (wid >> 2) * 48;

    float acc[2][6][4];
#pragma unroll
    for (int i = 0; i < 2; i++)
#pragma unroll
        for (int j = 0; j < 6; j++)
#pragma unroll
            for (int q = 0; q < 4; q++) acc[i][j][q] = 0.f;

    int aRow[4], aKq[4], bRow[3], bKq[3];
#pragma unroll
    for (int p = 0; p < 4; p++) { int idx = tid + 256*p; aRow[p] = idx >> 3; aKq[p] = idx & 7; }
#pragma unroll
    for (int p = 0; p < 3; p++) { int idx = tid + 256*p; bRow[p] = idx >> 3; bKq[p] = idx & 7; }

    float4 pa[4], pb[3];
#pragma unroll
    for (int p = 0; p < 4; p++) {
        size_t off = (size_t)(mb + aRow[p])*CC + aKq[p]*4;
        if (!is_out) pa[p] = *(const float4*)&g_xs[off];
        else {
            float4 r = *(const float4*)&g_r[off];
            float4 v = *(const float4*)&g_v[off];
            pa[p] = make_float4(r.x*v.x, r.y*v.y, r.z*v.z, r.w*v.w);
        }
    }
#pragma unroll
    for (int p = 0; p < 3; p++)
        pb[p] = *(const float4*)&Wsrc[(size_t)(nloc + bRow[p])*CC + bKq[p]*4];

    uint32_t ah_b = smem_u32(S.Ah), al_b = smem_u32(S.Al);
    uint32_t bh_b = smem_u32(S.Bh), bl_b = smem_u32(S.Bl);

#pragma unroll 1
    for (int st = 0; st < 6; st++) {
        __syncthreads();
#pragma unroll
        for (int p = 0; p < 4; p++) {
            uint32_t h0, l0, h1, l1;
            split2(pa[p].x, pa[p].y, h0, l0);
            split2(pa[p].z, pa[p].w, h1, l1);
            int bo = aRow[p]*(GSTRIDE*2) + aKq[p]*8;
            *(uint2*)((char*)S.Ah + bo) = make_uint2(h0, h1);
            *(uint2*)((char*)S.Al + bo) = make_uint2(l0, l1);
        }
#pragma unroll
        for (int p = 0; p < 3; p++) {
            uint32_t h0, l0, h1, l1;
            split2(pb[p].x, pb[p].y, h0, l0);
            split2(pb[p].z, pb[p].w, h1, l1);
            int bo = bRow[p]*(GSTRIDE*2) + bKq[p]*8;
            *(uint2*)((char*)S.Bh + bo) = make_uint2(h0, h1);
            *(uint2*)((char*)S.Bl + bo) = make_uint2(l0, l1);
        }
        __syncthreads();
        if (st < 5) {
            int k0 = (st + 1) * 32;
#pragma unroll
            for (int p = 0; p < 4; p++) {
                size_t off = (size_t)(mb + aRow[p])*CC + k0 + aKq[p]*4;
                if (!is_out) pa[p] = *(const float4*)&g_xs[off];
                else {
                    float4 r = *(const float4*)&g_r[off];
                    float4 v = *(const float4*)&g_v[off];
                    pa[p] = make_float4(r.x*v.x, r.y*v.y, r.z*v.z, r.w*v.w);
                }
            }
#pragma unroll
            for (int p = 0; p < 3; p++)
                pb[p] = *(const float4*)&Wsrc[(size_t)(nloc + bRow[p])*CC + k0 + bKq[p]*4];
        }
#pragma unroll 1
        for (int ks = 0; ks < 2; ks++) {
            int arow = warp_m + (lane & 15);
            int acol = ks*16 + (lane >> 4)*8;
            uint32_t ahf[2][4], alf[2][4];
#pragma unroll
            for (int mt = 0; mt < 2; mt++) {
                uint32_t bo = (uint32_t)((arow + mt*16)*(GSTRIDE*2) + acol*2);
                ldsm4(ahf[mt], ah_b + bo);
                ldsm4(alf[mt], al_b + bo);
            }
            int brow = warp_n + (lane & 7) + ((lane >> 4) << 3);
            int bcol = ks*16 + (((lane >> 3) & 1) << 3);
#pragma unroll
            for (int np = 0; np < 3; np++) {
                uint32_t bhf[4], blf[4];
                uint32_t bo = (uint32_t)((brow + np*16)*(GSTRIDE*2) + bcol*2);
                ldsm4(bhf, bh_b + bo);
                ldsm4(blf, bl_b + bo);
#pragma unroll
                for (int half = 0; half < 2; half++) {
                    int nt = np*2 + half;
#pragma unroll
                    for (int mt = 0; mt < 2; mt++) {
                        mma_bf16(acc[mt][nt], ahf[mt], bhf[half*2], bhf[half*2+1]);
                        mma_bf16(acc[mt][nt], ahf[mt], blf[half*2], blf[half*2+1]);
                        mma_bf16(acc[mt][nt], alf[mt], bhf[half*2], bhf[half*2+1]);
                    }
                }
            }
        }
    }

    int g = lane >> 2, tig = lane & 3;
#pragma unroll
    for (int mt = 0; mt < 2; mt++) {
#pragma unroll
        for (int nt = 0; nt < 6; nt++) {
            int m0 = mb + warp_m + mt*16 + g;
            int col = nloc + warp_n + nt*8 + tig*2;
            float2 v0 = make_float2(acc[mt][nt][0], acc[mt][nt][1]);
            float2 v1 = make_float2(acc[mt][nt][2], acc[mt][nt][3]);
            if (dosig) {
                v0.x = 1.f/(1.f+__expf(-v0.x)); v0.y = 1.f/(1.f+__expf(-v0.y));
                v1.x = 1.f/(1.f+__expf(-v1.x)); v1.y = 1.f/(1.f+__expf(-v1.y));
            }
            *(float2*)&Out[(size_t)m0*CC + col]     = v0;
            *(float2*)&Out[(size_t)(m0+8)*CC + col] = v1;
        }
    }
}

__global__ __launch_bounds__(256)
void gemm_kvr_h(const float* __restrict__ Wk, const float* __restrict__ Wv,
                const float* __restrict__ Wr) {
    __shared__ __align__(16) GemmSmem S;
    int nb = blockIdx.x * 96;
    int sel = nb / CC, nloc = nb % CC;
    const float* Wsrc = (sel == 0) ? Wk : (sel == 1) ? Wv : Wr;
    float* Out        = (sel == 0) ? g_k : (sel == 1) ? g_v : g_r;
    gemm_core(false, Wsrc, Out, nloc, blockIdx.y * 128, sel == 2, S);
}

__global__ __launch_bounds__(256)
void gemm_out_h(const float* __restrict__ Wo, float* __restrict__ outp) {
    __shared__ __align__(16) GemmSmem S;
    gemm_core(true, Wo, outp, blockIdx.x * 96, blockIdx.y * 128, false, S);
}

// ---------------- 4. WKV chunked parallel scan (chunk=48, 4-deep pipeline) -
__device__ __forceinline__ void chunk_map(int ci, int j, int& t0, int& stp) {
    if (j == 0) { t0 = ci * CS; stp = 1; }
    else        { t0 = ((ci & 1) * CS) * CW + (ci >> 1); stp = CW; }
}

__global__ void wkv_pass1(const float* __restrict__ sd, int j) {
    int ci = blockIdx.x, b = blockIdx.y, c = threadIdx.x;
    float w  = sd[c] * (1.0f/(float)CT);
    float wl = w * L2E;
    float S = 0.f, Sq = 0.f, off = -wl;
    size_t base = (size_t)b*CT*CC + c;
    int t0, stp; chunk_map(ci, j, t0, stp);
    size_t o = base + (size_t)t0*CC;
    size_t ostep = (size_t)stp*CC;
    float kb[4], vb[4];
#pragma unroll
    for (int p = 0; p < 4; p++) { kb[p] = g_k[o + p*ostep]; vb[p] = g_v[o + p*ostep]; }
#pragma unroll 1
    for (int i = 0; i < CS; i += 4) {
        float kn[4], vn[4];
        if (i + 4 < CS) {
            size_t on = o + 4*ostep;
#pragma unroll
            for (int p = 0; p < 4; p++) { kn[p] = g_k[on + p*ostep]; vn[p] = g_v[on + p*ostep]; }
        }
#pragma unroll
        for (int p = 0; p < 4; p++) {
            float E = exp2f(fmaf(kb[p], L2E, off));
            S  = fmaf(E, vb[p], S);
            Sq += E;
            off -= wl;
        }
#pragma unroll
        for (int p = 0; p < 4; p++) { kb[p] = kn[p]; vb[p] = vn[p]; }
        o += 4*ostep;
    }
    int sidx = (b*NCHUNK + ci)*CC + c;
    g_sp[sidx] = S; g_sq[sidx] = Sq;
}

__global__ void wkv_cscan(const float* __restrict__ sd) {
    int b = blockIdx.x, c = threadIdx.x;
    float w  = sd[c] * (1.0f/(float)CT);
    float Wc = (float)CS * w;
    float p = 0.f, q = 0.f, o = -1e38f;
    for (int ci = 0; ci < NCHUNK; ci++) {
        int sidx = (b*NCHUNK + ci)*CC + c;
        float Pc = g_sp[sidx], Qc = g_sq[sidx];
        g_sp[sidx] = p; g_sq[sidx] = q; g_so[sidx] = o;
        float o1 = o + Wc;
        float no = fmaxf(o1, Wc);
        float e1 = exp2f((o1 - no)*L2E);
        float e2 = exp2f((Wc - no)*L2E);
        p = fmaf(e1, p, e2*Pc);
        q = fmaf(e1, q, e2*Qc);
        o = no;
    }
}

__global__ void wkv_pass2(const float* __restrict__ sd, const float* __restrict__ sf,
                          int j) {
    int ci = blockIdx.x, b = blockIdx.y, c = threadIdx.x;
    float w  = sd[c] * (1.0f/(float)CT);
    float u  = sf[c] * (1.0f/(float)CT);
    float wl = w * L2E;
    float c1 = exp2f(-(u + w)*L2E);
    int sidx = (b*NCHUNK + ci)*CC + c;
    float p = g_sp[sidx], q = g_sq[sidx], o = g_so[sidx];
    float offu;
    if (o < -1e30f) { p = 0.f; q = 0.f; offu = u*L2E; }
    else            { offu = (u - o)*L2E; }
    size_t base = (size_t)b*CT*CC + c;
    int t0, stp; chunk_map(ci, j, t0, stp);
    size_t oc = base + (size_t)t0*CC;
    size_t ostep = (size_t)stp*CC;
    float kb[4], vb[4];
#pragma unroll
    for (int pp = 0; pp < 4; pp++) { kb[pp] = g_k[oc + pp*ostep]; vb[pp] = g_v[oc + pp*ostep]; }
#pragma unroll 1
    for (int i = 0; i < CS; i += 4) {
        float kn[4], vn[4];
        if (i + 4 < CS) {
            size_t on = oc + 4*ostep;
#pragma unroll
            for (int pp = 0; pp < 4; pp++) { kn[pp] = g_k[on + pp*ostep]; vn[pp] = g_v[on + pp*ostep]; }
        }
#pragma unroll
        for (int pp = 0; pp < 4; pp++) {
            float Eu = exp2f(fmaf(kb[pp], L2E, offu));
            float y  = __fdividef(fmaf(Eu, vb[pp], p), q + Eu);
            g_v[oc + pp*ostep] = y;
            float E = Eu * c1;
            p = fmaf(E, vb[pp], p);
            q += E;
            offu -= wl;
        }
#pragma unroll
        for (int pp = 0; pp < 4; pp++) { kb[pp] = kn[pp]; vb[pp] = vn[pp]; }
        oc += 4*ostep;
    }
}

// ---------------- launcher -------------------------------------------------
extern "C" void kernel_launch(void* const* d_in, const int* in_sizes, int n_in,
                              void* d_out, int out_size) {
    const float* x     = (const float*)d_in[0];
    const float* alpha = (const float*)d_in[1];
    const float* w1    = (const float*)d_in[2];
    const float* w3    = (const float*)d_in[3];
    const float* w5    = (const float*)d_in[4];
    const float* Wk    = (const float*)d_in[5];
    const float* Wv    = (const float*)d_in[6];
    const float* Wr    = (const float*)d_in[7];
    const float* Wo    = (const float*)d_in[8];
    const float* sd    = (const float*)d_in[9];
    const float* sf    = (const float*)d_in[10];
    float* out = (float*)d_out;

    combine_cw<<<(CC*25 + 255)/256, 256>>>(alpha, w1, w3, w5);
    conv5<<<dim3(CH/2, CB), CC>>>(x);
    gemm_kvr_h<<<dim3(6, CM/128), 256>>>(Wk, Wv, Wr);

    // scan j = 0: row-major
    wkv_pass1<<<dim3(NCHUNK, CB), CC>>>(sd, 0);
    wkv_cscan<<<CB, CC>>>(sd);
    wkv_pass2<<<dim3(NCHUNK, CB), CC>>>(sd, sf, 0);

    // scan j = 1: column-major
    wkv_pass1<<<dim3(NCHUNK, CB), CC>>>(sd + CC, 1);
    wkv_cscan<<<CB, CC>>>(sd + CC);
    wkv_pass2<<<dim3(NCHUNK, CB), CC>>>(sd + CC, sf + CC, 1);

    gemm_out_h<<<dim3(2, CM/128), 256>>>(Wo, out);
}

// round 13
// speedup vs baseline: 1.2980x; 1.0499x over previous
#include <cuda_runtime.h>
#include <cuda_bf16.h>
#include <cstdint>

// Problem constants (fixed by setup_inputs)
#define CB 8
#define CH 96
#define CW 96
#define CC 192
#define CT (CH*CW)          // 9216
#define CM (CB*CT)          // 73728
#define L2E 1.4426950408889634f
#define NCHUNK 192
#define CS 48               // wkv chunk size

// ---------------- scratch (static __device__; no runtime allocation) -------
__device__ __align__(16) float g_xs[CM*CC];     // omni-shift output
__device__ __align__(16) float g_k [CM*CC];
__device__ __align__(16) float g_v [CM*CC];     // v -> y1 -> y2 (in-place)
__device__ __align__(16) float g_r [CM*CC];     // sigmoid(r)
__device__ __align__(16) float g_sp[CB*NCHUNK*CC];
__device__ __align__(16) float g_sq[CB*NCHUNK*CC];
__device__ __align__(16) float g_so[CB*NCHUNK*CC];

// ---------------- 2. depthwise 5x5 conv (weights combined inline) ----------
// grid (CH/2, CB), 192 threads; 6-row register sliding window, 2 output rows.
__global__ __launch_bounds__(CC) void conv5(const float* __restrict__ x,
                                            const float* __restrict__ alpha,
                                            const float* __restrict__ w1,
                                            const float* __restrict__ w3,
                                            const float* __restrict__ w5) {
    int h0 = blockIdx.x * 2, b = blockIdx.y, c = threadIdx.x;
    float a0c = alpha[0], a1c = alpha[1], a2c = alpha[2], a3c = alpha[3];
    float wr[25];
#pragma unroll
    for (int tap = 0; tap < 25; tap++) {
        int dy = tap / 5, dx = tap % 5;
        float v = a3c * w5[c*25 + tap];
        if (dy == 2 && dx == 2) v += a0c + a1c * w1[c];
        if (dy >= 1 && dy <= 3 && dx >= 1 && dx <= 3)
            v += a2c * w3[c*9 + (dy-1)*3 + (dx-1)];
        wr[tap] = v;
    }
    bool rv[6];
#pragma unroll
    for (int r = 0; r < 6; r++) rv[r] = (unsigned)(h0 - 2 + r) < CH;
    const float* xb = x    + (size_t)b*CT*CC + c;
    float*       ob = g_xs + (size_t)b*CT*CC + c;
    float win[6][5];
#pragma unroll
    for (int r = 0; r < 6; r++) {
        int hy = h0 - 2 + r;
        win[r][0] = 0.f; win[r][1] = 0.f;
        win[r][2] = rv[r] ? xb[(size_t)(hy*CW + 0)*CC] : 0.f;
        win[r][3] = rv[r] ? xb[(size_t)(hy*CW + 1)*CC] : 0.f;
        win[r][4] = 0.f;
    }
#pragma unroll 4
    for (int w = 0; w < CW; w++) {
        int wx = w + 2;
        bool cv = wx < CW;
#pragma unroll
        for (int r = 0; r < 6; r++)
            win[r][4] = (rv[r] && cv) ? xb[(size_t)((h0-2+r)*CW + wx)*CC] : 0.f;
        float a0 = 0.f, a1 = 0.f;
#pragma unroll
        for (int dy = 0; dy < 5; dy++)
#pragma unroll
            for (int j = 0; j < 5; j++) {
                a0 = fmaf(win[dy][j],   wr[dy*5+j], a0);
                a1 = fmaf(win[dy+1][j], wr[dy*5+j], a1);
            }
        ob[(size_t)(h0*CW + w)*CC]     = a0;
        ob[(size_t)((h0+1)*CW + w)*CC] = a1;
#pragma unroll
        for (int r = 0; r < 6; r++)
#pragma unroll
            for (int j = 0; j < 4; j++)
                win[r][j] = win[r][j+1];
    }
}

// ================= HMMA bf16 GEMM (R10 485us version, verbatim) ============
#define GSTRIDE 40   // smem row stride in bf16 elements (80 bytes)

__device__ __forceinline__ void split2(float a, float b, uint32_t& hi, uint32_t& lo) {
    __nv_bfloat16 ha = __float2bfloat16(a), hb = __float2bfloat16(b);
    float ra = a - __bfloat162float(ha), rb = b - __bfloat162float(hb);
    __nv_bfloat16 la = __float2bfloat16(ra), lb = __float2bfloat16(rb);
    hi = ((uint32_t)__bfloat16_as_ushort(hb) << 16) | (uint32_t)__bfloat16_as_ushort(ha);
    lo = ((uint32_t)__bfloat16_as_ushort(lb) << 16) | (uint32_t)__bfloat16_as_ushort(la);
}
__device__ __forceinline__ uint32_t smem_u32(const void* p) {
    uint32_t a;
    asm("{ .reg .u64 t; cvta.to.shared.u64 t, %1; cvt.u32.u64 %0, t; }" : "=r"(a) : "l"(p));
    return a;
}
__device__ __forceinline__ void ldsm4(uint32_t* r, uint32_t addr) {
    asm volatile("ldmatrix.sync.aligned.m8n8.x4.shared.b16 {%0,%1,%2,%3}, [%4];"
        : "=r"(r[0]), "=r"(r[1]), "=r"(r[2]), "=r"(r[3]) : "r"(addr));
}
__device__ __forceinline__ void mma_bf16(float* c, const uint32_t* a, uint32_t b0, uint32_t b1) {
    asm volatile("mma.sync.aligned.m16n8k16.row.col.f32.bf16.bf16.f32 "
        "{%0,%1,%2,%3}, {%4,%5,%6,%7}, {%8,%9}, {%0,%1,%2,%3};"
        : "+f"(c[0]), "+f"(c[1]), "+f"(c[2]), "+f"(c[3])
        : "r"(a[0]), "r"(a[1]), "r"(a[2]), "r"(a[3]), "r"(b0), "r"(b1));
}

struct GemmSmem {
    uint16_t Ah[128*GSTRIDE];
    uint16_t Al[128*GSTRIDE];
    uint16_t Bh[96*GSTRIDE];
    uint16_t Bl[96*GSTRIDE];
};

__device__ __forceinline__ void gemm_core(bool is_out, const float* __restrict__ Wsrc,
                                          float* __restrict__ Out, int nloc, int mb,
                                          bool dosig, GemmSmem& S) {
    int tid = threadIdx.x, lane = tid & 31, wid = tid >> 5;
    int warp_m = (wid & 3) * 32, warp_n = (wid >> 2) * 48;

    float acc[2][6][4];
#pragma unroll
    for (int i = 0; i < 2; i++)
#pragma unroll
        for (int j = 0; j < 6; j++)
#pragma unroll
            for (int q = 0; q < 4; q++) acc[i][j][q] = 0.f;

    int aRow[4], aKq[4], bRow[3], bKq[3];
#pragma unroll
    for (int p = 0; p < 4; p++) { int idx = tid + 256*p; aRow[p] = idx >> 3; aKq[p] = idx & 7; }
#pragma unroll
    for (int p = 0; p < 3; p++) { int idx = tid + 256*p; bRow[p] = idx >> 3; bKq[p] = idx & 7; }

    float4 pa[4], pb[3];
#pragma unroll
    for (int p = 0; p < 4; p++) {
        size_t off = (size_t)(mb + aRow[p])*CC + aKq[p]*4;
        if (!is_out) pa[p] = *(const float4*)&g_xs[off];
        else {
            float4 r = *(const float4*)&g_r[off];
            float4 v = *(const float4*)&g_v[off];
            pa[p] = make_float4(r.x*v.x, r.y*v.y, r.z*v.z, r.w*v.w);
        }
    }
#pragma unroll
    for (int p = 0; p < 3; p++)
        pb[p] = *(const float4*)&Wsrc[(size_t)(nloc + bRow[p])*CC + bKq[p]*4];

    uint32_t ah_b = smem_u32(S.Ah), al_b = smem_u32(S.Al);
    uint32_t bh_b = smem_u32(S.Bh), bl_b = smem_u32(S.Bl);

#pragma unroll 1
    for (int st = 0; st < 6; st++) {
        __syncthreads();
#pragma unroll
        for (int p = 0; p < 4; p++) {
            uint32_t h0, l0, h1, l1;
            split2(pa[p].x, pa[p].y, h0, l0);
            split2(pa[p].z, pa[p].w, h1, l1);
            int bo = aRow[p]*(GSTRIDE*2) + aKq[p]*8;
            *(uint2*)((char*)S.Ah + bo) = make_uint2(h0, h1);
            *(uint2*)((char*)S.Al + bo) = make_uint2(l0, l1);
        }
#pragma unroll
        for (int p = 0; p < 3; p++) {
            uint32_t h0, l0, h1, l1;
            split2(pb[p].x, pb[p].y, h0, l0);
            split2(pb[p].z, pb[p].w, h1, l1);
            int bo = bRow[p]*(GSTRIDE*2) + bKq[p]*8;
            *(uint2*)((char*)S.Bh + bo) = make_uint2(h0, h1);
            *(uint2*)((char*)S.Bl + bo) = make_uint2(l0, l1);
        }
        __syncthreads();
        if (st < 5) {
            int k0 = (st + 1) * 32;
#pragma unroll
            for (int p = 0; p < 4; p++) {
                size_t off = (size_t)(mb + aRow[p])*CC + k0 + aKq[p]*4;
                if (!is_out) pa[p] = *(const float4*)&g_xs[off];
                else {
                    float4 r = *(const float4*)&g_r[off];
                    float4 v = *(const float4*)&g_v[off];
                    pa[p] = make_float4(r.x*v.x, r.y*v.y, r.z*v.z, r.w*v.w);
                }
            }
#pragma unroll
            for (int p = 0; p < 3; p++)
                pb[p] = *(const float4*)&Wsrc[(size_t)(nloc + bRow[p])*CC + k0 + bKq[p]*4];
        }
#pragma unroll 1
        for (int ks = 0; ks < 2; ks++) {
            int arow = warp_m + (lane & 15);
            int acol = ks*16 + (lane >> 4)*8;
            uint32_t ahf[2][4], alf[2][4];
#pragma unroll
            for (int mt = 0; mt < 2; mt++) {
                uint32_t bo = (uint32_t)((arow + mt*16)*(GSTRIDE*2) + acol*2);
                ldsm4(ahf[mt], ah_b + bo);
                ldsm4(alf[mt], al_b + bo);
            }
            int brow = warp_n + (lane & 7) + ((lane >> 4) << 3);
            int bcol = ks*16 + (((lane >> 3) & 1) << 3);
#pragma unroll
            for (int np = 0; np < 3; np++) {
                uint32_t bhf[4], blf[4];
                uint32_t bo = (uint32_t)((brow + np*16)*(GSTRIDE*2) + bcol*2);
                ldsm4(bhf, bh_b + bo);
                ldsm4(blf, bl_b + bo);
#pragma unroll
                for (int half = 0; half < 2; half++) {
                    int nt = np*2 + half;
#pragma unroll
                    for (int mt = 0; mt < 2; mt++) {
                        mma_bf16(acc[mt][nt], ahf[mt], bhf[half*2], bhf[half*2+1]);
                        mma_bf16(acc[mt][nt], ahf[mt], blf[half*2], blf[half*2+1]);
                        mma_bf16(acc[mt][nt], alf[mt], bhf[half*2], bhf[half*2+1]);
                    }
                }
            }
        }
    }

    int g = lane >> 2, tig = lane & 3;
#pragma unroll
    for (int mt = 0; mt < 2; mt++) {
#pragma unroll
        for (int nt = 0; nt < 6; nt++) {
            int m0 = mb + warp_m + mt*16 + g;
            int col = nloc + warp_n + nt*8 + tig*2;
            float2 v0 = make_float2(acc[mt][nt][0], acc[mt][nt][1]);
            float2 v1 = make_float2(acc[mt][nt][2], acc[mt][nt][3]);
            if (dosig) {
                v0.x = 1.f/(1.f+__expf(-v0.x)); v0.y = 1.f/(1.f+__expf(-v0.y));
                v1.x = 1.f/(1.f+__expf(-v1.x)); v1.y = 1.f/(1.f+__expf(-v1.y));
            }
            *(float2*)&Out[(size_t)m0*CC + col]     = v0;
            *(float2*)&Out[(size_t)(m0+8)*CC + col] = v1;
        }
    }
}

__global__ __launch_bounds__(256)
void gemm_kvr_h(const float* __restrict__ Wk, const float* __restrict__ Wv,
                const float* __restrict__ Wr) {
    __shared__ __align__(16) GemmSmem S;
    int nb = blockIdx.x * 96;
    int sel = nb / CC, nloc = nb % CC;
    const float* Wsrc = (sel == 0) ? Wk : (sel == 1) ? Wv : Wr;
    float* Out        = (sel == 0) ? g_k : (sel == 1) ? g_v : g_r;
    gemm_core(false, Wsrc, Out, nloc, blockIdx.y * 128, sel == 2, S);
}

__global__ __launch_bounds__(256)
void gemm_out_h(const float* __restrict__ Wo, float* __restrict__ outp) {
    __shared__ __align__(16) GemmSmem S;
    gemm_core(true, Wo, outp, blockIdx.x * 96, blockIdx.y * 128, false, S);
}

// ---------------- 4. WKV chunked parallel scan (float2: 2 channels/thread) -
__device__ __forceinline__ void chunk_map(int ci, int j, int& t0, int& stp) {
    if (j == 0) { t0 = ci * CS; stp = 1; }
    else        { t0 = ((ci & 1) * CS) * CW + (ci >> 1); stp = CW; }
}

__global__ void wkv_pass1(const float* __restrict__ sd, int j) {
    int ci = blockIdx.x, b = blockIdx.y, c2 = threadIdx.x * 2;
    float2 wv = *(const float2*)&sd[c2];
    float wlx = wv.x * (1.0f/(float)CT) * L2E;
    float wly = wv.y * (1.0f/(float)CT) * L2E;
    float Sx = 0.f, Sy = 0.f, Qx = 0.f, Qy = 0.f;
    float ofx = -wlx, ofy = -wly;
    size_t base = (size_t)b*CT*CC + c2;
    int t0, stp; chunk_map(ci, j, t0, stp);
    size_t o = base + (size_t)t0*CC;
    size_t ostep = (size_t)stp*CC;
    float2 kb[4], vb[4];
#pragma unroll
    for (int p = 0; p < 4; p++) {
        kb[p] = *(const float2*)&g_k[o + p*ostep];
        vb[p] = *(const float2*)&g_v[o + p*ostep];
    }
#pragma unroll 1
    for (int i = 0; i < CS; i += 4) {
        float2 kn[4], vn[4];
        if (i + 4 < CS) {
            size_t on = o + 4*ostep;
#pragma unroll
            for (int p = 0; p < 4; p++) {
                kn[p] = *(const float2*)&g_k[on + p*ostep];
                vn[p] = *(const float2*)&g_v[on + p*ostep];
            }
        }
#pragma unroll
        for (int p = 0; p < 4; p++) {
            float Ex = exp2f(fmaf(kb[p].x, L2E, ofx));
            float Ey = exp2f(fmaf(kb[p].y, L2E, ofy));
            Sx = fmaf(Ex, vb[p].x, Sx);
            Sy = fmaf(Ey, vb[p].y, Sy);
            Qx += Ex; Qy += Ey;
            ofx -= wlx; ofy -= wly;
        }
#pragma unroll
        for (int p = 0; p < 4; p++) { kb[p] = kn[p]; vb[p] = vn[p]; }
        o += 4*ostep;
    }
    int sidx = (b*NCHUNK + ci)*CC + c2;
    *(float2*)&g_sp[sidx] = make_float2(Sx, Sy);
    *(float2*)&g_sq[sidx] = make_float2(Qx, Qy);
}

__global__ void wkv_cscan(const float* __restrict__ sd) {
    int b = blockIdx.x, c = threadIdx.x;
    float w  = sd[c] * (1.0f/(float)CT);
    float Wc = (float)CS * w;
    float p = 0.f, q = 0.f, o = -1e38f;
    for (int ci = 0; ci < NCHUNK; ci++) {
        int sidx = (b*NCHUNK + ci)*CC + c;
        float Pc = g_sp[sidx], Qc = g_sq[sidx];
        g_sp[sidx] = p; g_sq[sidx] = q; g_so[sidx] = o;
        float o1 = o + Wc;
        float no = fmaxf(o1, Wc);
        float e1 = exp2f((o1 - no)*L2E);
        float e2 = exp2f((Wc - no)*L2E);
        p = fmaf(e1, p, e2*Pc);
        q = fmaf(e1, q, e2*Qc);
        o = no;
    }
}

__global__ void wkv_pass2(const float* __restrict__ sd, const float* __restrict__ sf,
                          int j) {
    int ci = blockIdx.x, b = blockIdx.y, c2 = threadIdx.x * 2;
    float2 wv = *(const float2*)&sd[c2];
    float2 uv = *(const float2*)&sf[c2];
    float wx = wv.x * (1.0f/(float)CT), wy = wv.y * (1.0f/(float)CT);
    float ux = uv.x * (1.0f/(float)CT), uy = uv.y * (1.0f/(float)CT);
    float wlx = wx * L2E, wly = wy * L2E;
    float c1x = exp2f(-(ux + wx)*L2E);
    float c1y = exp2f(-(uy + wy)*L2E);
    int sidx = (b*NCHUNK + ci)*CC + c2;
    float2 pv = *(float2*)&g_sp[sidx];
    float2 qv = *(float2*)&g_sq[sidx];
    float2 ov = *(float2*)&g_so[sidx];
    float px = pv.x, py = pv.y, qx = qv.x, qy = qv.y;
    float ofux, ofuy;
    if (ov.x < -1e30f) { px = 0.f; qx = 0.f; ofux = ux*L2E; }
    else               { ofux = (ux - ov.x)*L2E; }
    if (ov.y < -1e30f) { py = 0.f; qy = 0.f; ofuy = uy*L2E; }
    else               { ofuy = (uy - ov.y)*L2E; }
    size_t base = (size_t)b*CT*CC + c2;
    int t0, stp; chunk_map(ci, j, t0, stp);
    size_t oc = base + (size_t)t0*CC;
    size_t ostep = (size_t)stp*CC;
    float2 kb[4], vb[4];
#pragma unroll
    for (int p = 0; p < 4; p++) {
        kb[p] = *(const float2*)&g_k[oc + p*ostep];
        vb[p] = *(const float2*)&g_v[oc + p*ostep];
    }
#pragma unroll 1
    for (int i = 0; i < CS; i += 4) {
        float2 kn[4], vn[4];
        if (i + 4 < CS) {
            size_t on = oc + 4*ostep;
#pragma unroll
            for (int p = 0; p < 4; p++) {
                kn[p] = *(const float2*)&g_k[on + p*ostep];
                vn[p] = *(const float2*)&g_v[on + p*ostep];
            }
        }
#pragma unroll
        for (int p = 0; p < 4; p++) {
            float Eux = exp2f(fmaf(kb[p].x, L2E, ofux));
            float Euy = exp2f(fmaf(kb[p].y, L2E, ofuy));
            float yx = __fdividef(fmaf(Eux, vb[p].x, px), qx + Eux);
            float yy = __fdividef(fmaf(Euy, vb[p].y, py), qy + Euy);
            *(float2*)&g_v[oc + p*ostep] = make_float2(yx, yy);
            float Ex = Eux * c1x, Ey = Euy * c1y;
            px = fmaf(Ex, vb[p].x, px);
            py = fmaf(Ey, vb[p].y, py);
            qx += Ex; qy += Ey;
            ofux -= wlx; ofuy -= wly;
        }
#pragma unroll
        for (int p = 0; p < 4; p++) { kb[p] = kn[p]; vb[p] = vn[p]; }
        oc += 4*ostep;
    }
}

// ---------------- launcher -------------------------------------------------
extern "C" void kernel_launch(void* const* d_in, const int* in_sizes, int n_in,
                              void* d_out, int out_size) {
    const float* x     = (const float*)d_in[0];
    const float* alpha = (const float*)d_in[1];
    const float* w1    = (const float*)d_in[2];
    const float* w3    = (const float*)d_in[3];
    const float* w5    = (const float*)d_in[4];
    const float* Wk    = (const float*)d_in[5];
    const float* Wv    = (const float*)d_in[6];
    const float* Wr    = (const float*)d_in[7];
    const float* Wo    = (const float*)d_in[8];
    const float* sd    = (const float*)d_in[9];
    const float* sf    = (const float*)d_in[10];
    float* out = (float*)d_out;

    conv5<<<dim3(CH/2, CB), CC>>>(x, alpha, w1, w3, w5);
    gemm_kvr_h<<<dim3(6, CM/128), 256>>>(Wk, Wv, Wr);

    // scan j = 0: row-major
    wkv_pass1<<<dim3(NCHUNK, CB), CC/2>>>(sd, 0);
    wkv_cscan<<<CB, CC>>>(sd);
    wkv_pass2<<<dim3(NCHUNK, CB), CC/2>>>(sd, sf, 0);

    // scan j = 1: column-major
    wkv_pass1<<<dim3(NCHUNK, CB), CC/2>>>(sd + CC, 1);
    wkv_cscan<<<CB, CC>>>(sd + CC);
    wkv_pass2<<<dim3(NCHUNK, CB), CC/2>>>(sd + CC, sf + CC, 1);

    gemm_out_h<<<dim3(2, CM/128), 256>>>(Wo, out);
}

// round 14
// speedup vs baseline: 1.4024x; 1.0805x over previous
#include <cuda_runtime.h>
#include <cuda_bf16.h>
#include <cstdint>

// Problem constants (fixed by setup_inputs)
#define CB 8
#define CH 96
#define CW 96
#define CC 192
#define CT (CH*CW)          // 9216
#define CM (CB*CT)          // 73728
#define L2E 1.4426950408889634f
#define NCHUNK 192
#define CS 48               // wkv chunk size

// ---------------- scratch (static __device__; no runtime allocation) -------
__device__ __align__(16) float g_xs[CM*CC];     // omni-shift output
__device__ __align__(16) float g_k [CM*CC];
__device__ __align__(16) float g_v [CM*CC];     // v -> y1 -> y2 (in-place)
__device__ __align__(16) float g_r [CM*CC];     // sigmoid(r)
__device__ __align__(16) float g_sp [CB*NCHUNK*CC];  // scaled chunk summaries (p)
__device__ __align__(16) float g_sq [CB*NCHUNK*CC];  // scaled chunk summaries (q)
__device__ __align__(16) float g_so [CB*NCHUNK*CC];  // exclusive prefix (p)
__device__ __align__(16) float g_sq2[CB*NCHUNK*CC];  // exclusive prefix (q)

// ---------------- 2. depthwise 5x5 conv (weights combined inline) ----------
__global__ __launch_bounds__(CC) void conv5(const float* __restrict__ x,
                                            const float* __restrict__ alpha,
                                            const float* __restrict__ w1,
                                            const float* __restrict__ w3,
                                            const float* __restrict__ w5) {
    int h0 = blockIdx.x * 2, b = blockIdx.y, c = threadIdx.x;
    float a0c = alpha[0], a1c = alpha[1], a2c = alpha[2], a3c = alpha[3];
    float wr[25];
#pragma unroll
    for (int tap = 0; tap < 25; tap++) {
        int dy = tap / 5, dx = tap % 5;
        float v = a3c * w5[c*25 + tap];
        if (dy == 2 && dx == 2) v += a0c + a1c * w1[c];
        if (dy >= 1 && dy <= 3 && dx >= 1 && dx <= 3)
            v += a2c * w3[c*9 + (dy-1)*3 + (dx-1)];
        wr[tap] = v;
    }
    bool rv[6];
#pragma unroll
    for (int r = 0; r < 6; r++) rv[r] = (unsigned)(h0 - 2 + r) < CH;
    const float* xb = x    + (size_t)b*CT*CC + c;
    float*       ob = g_xs + (size_t)b*CT*CC + c;
    float win[6][5];
#pragma unroll
    for (int r = 0; r < 6; r++) {
        int hy = h0 - 2 + r;
        win[r][0] = 0.f; win[r][1] = 0.f;
        win[r][2] = rv[r] ? xb[(size_t)(hy*CW + 0)*CC] : 0.f;
        win[r][3] = rv[r] ? xb[(size_t)(hy*CW + 1)*CC] : 0.f;
        win[r][4] = 0.f;
    }
#pragma unroll 4
    for (int w = 0; w < CW; w++) {
        int wx = w + 2;
        bool cv = wx < CW;
#pragma unroll
        for (int r = 0; r < 6; r++)
            win[r][4] = (rv[r] && cv) ? xb[(size_t)((h0-2+r)*CW + wx)*CC] : 0.f;
        float a0 = 0.f, a1 = 0.f;
#pragma unroll
        for (int dy = 0; dy < 5; dy++)
#pragma unroll
            for (int j = 0; j < 5; j++) {
                a0 = fmaf(win[dy][j],   wr[dy*5+j], a0);
                a1 = fmaf(win[dy+1][j], wr[dy*5+j], a1);
            }
        ob[(size_t)(h0*CW + w)*CC]     = a0;
        ob[(size_t)((h0+1)*CW + w)*CC] = a1;
#pragma unroll
        for (int r = 0; r < 6; r++)
#pragma unroll
            for (int j = 0; j < 4; j++)
                win[r][j] = win[r][j+1];
    }
}

// ================= HMMA bf16 GEMM (R10 485us version, verbatim) ============
#define GSTRIDE 40   // smem row stride in bf16 elements (80 bytes)

__device__ __forceinline__ void split2(float a, float b, uint32_t& hi, uint32_t& lo) {
    __nv_bfloat16 ha = __float2bfloat16(a), hb = __float2bfloat16(b);
    float ra = a - __bfloat162float(ha), rb = b - __bfloat162float(hb);
    __nv_bfloat16 la = __float2bfloat16(ra), lb = __float2bfloat16(rb);
    hi = ((uint32_t)__bfloat16_as_ushort(hb) << 16) | (uint32_t)__bfloat16_as_ushort(ha);
    lo = ((uint32_t)__bfloat16_as_ushort(lb) << 16) | (uint32_t)__bfloat16_as_ushort(la);
}
__device__ __forceinline__ uint32_t smem_u32(const void* p) {
    uint32_t a;
    asm("{ .reg .u64 t; cvta.to.shared.u64 t, %1; cvt.u32.u64 %0, t; }" : "=r"(a) : "l"(p));
    return a;
}
__device__ __forceinline__ void ldsm4(uint32_t* r, uint32_t addr) {
    asm volatile("ldmatrix.sync.aligned.m8n8.x4.shared.b16 {%0,%1,%2,%3}, [%4];"
        : "=r"(r[0]), "=r"(r[1]), "=r"(r[2]), "=r"(r[3]) : "r"(addr));
}
__device__ __forceinline__ void mma_bf16(float* c, const uint32_t* a, uint32_t b0, uint32_t b1) {
    asm volatile("mma.sync.aligned.m16n8k16.row.col.f32.bf16.bf16.f32 "
        "{%0,%1,%2,%3}, {%4,%5,%6,%7}, {%8,%9}, {%0,%1,%2,%3};"
        : "+f"(c[0]), "+f"(c[1]), "+f"(c[2]), "+f"(c[3])
        : "r"(a[0]), "r"(a[1]), "r"(a[2]), "r"(a[3]), "r"(b0), "r"(b1));
}

struct GemmSmem {
    uint16_t Ah[128*GSTRIDE];
    uint16_t Al[128*GSTRIDE];
    uint16_t Bh[96*GSTRIDE];
    uint16_t Bl[96*GSTRIDE];
};

__device__ __forceinline__ void gemm_core(bool is_out, const float* __restrict__ Wsrc,
                                          float* __restrict__ Out, int nloc, int mb,
                                          bool dosig, GemmSmem& S) {
    int tid = threadIdx.x, lane = tid & 31, wid = tid >> 5;
    int warp_m = (wid & 3) * 32, warp_n = (wid >> 2) * 48;

    float acc[2][6][4];
#pragma unroll
    for (int i = 0; i < 2; i++)
#pragma unroll
        for (int j = 0; j < 6; j++)
#pragma unroll
            for (int q = 0; q < 4; q++) acc[i][j][q] = 0.f;

    int aRow[4], aKq[4], bRow[3], bKq[3];
#pragma unroll
    for (int p = 0; p < 4; p++) { int idx = tid + 256*p; aRow[p] = idx >> 3; aKq[p] = idx & 7; }
#pragma unroll
    for (int p = 0; p < 3; p++) { int idx = tid + 256*p; bRow[p] = idx >> 3; bKq[p] = idx & 7; }

    float4 pa[4], pb[3];
#pragma unroll
    for (int p = 0; p < 4; p++) {
        size_t off = (size_t)(mb + aRow[p])*CC + aKq[p]*4;
        if (!is_out) pa[p] = *(const float4*)&g_xs[off];
        else {
            float4 r = *(const float4*)&g_r[off];
            float4 v = *(const float4*)&g_v[off];
            pa[p] = make_float4(r.x*v.x, r.y*v.y, r.z*v.z, r.w*v.w);
        }
    }
#pragma unroll
    for (int p = 0; p < 3; p++)
        pb[p] = *(const float4*)&Wsrc[(size_t)(nloc + bRow[p])*CC + bKq[p]*4];

    uint32_t ah_b = smem_u32(S.Ah), al_b = smem_u32(S.Al);
    uint32_t bh_b = smem_u32(S.Bh), bl_b = smem_u32(S.Bl);

#pragma unroll 1
    for (int st = 0; st < 6; st++) {
        __syncthreads();
#pragma unroll
        for (int p = 0; p < 4; p++) {
            uint32_t h0, l0, h1, l1;
            split2(pa[p].x, pa[p].y, h0, l0);
            split2(pa[p].z, pa[p].w, h1, l1);
            int bo = aRow[p]*(GSTRIDE*2) + aKq[p]*8;
            *(uint2*)((char*)S.Ah + bo) = make_uint2(h0, h1);
            *(uint2*)((char*)S.Al + bo) = make_uint2(l0, l1);
        }
#pragma unroll
        for (int p = 0; p < 3; p++) {
            uint32_t h0, l0, h1, l1;
            split2(pb[p].x, pb[p].y, h0, l0);
            split2(pb[p].z, pb[p].w, h1, l1);
            int bo = bRow[p]*(GSTRIDE*2) + bKq[p]*8;
            *(uint2*)((char*)S.Bh + bo) = make_uint2(h0, h1);
            *(uint2*)((char*)S.Bl + bo) = make_uint2(l0, l1);
        }
        __syncthreads();
        if (st < 5) {
            int k0 = (st + 1) * 32;
#pragma unroll
            for (int p = 0; p < 4; p++) {
                size_t off = (size_t)(mb + aRow[p])*CC + k0 + aKq[p]*4;
                if (!is_out) pa[p] = *(const float4*)&g_xs[off];
                else {
                    float4 r = *(const float4*)&g_r[off];
                    float4 v = *(const float4*)&g_v[off];
                    pa[p] = make_float4(r.x*v.x, r.y*v.y, r.z*v.z, r.w*v.w);
                }
            }
#pragma unroll
            for (int p = 0; p < 3; p++)
                pb[p] = *(const float4*)&Wsrc[(size_t)(nloc + bRow[p])*CC + k0 + bKq[p]*4];
        }
#pragma unroll 1
        for (int ks = 0; ks < 2; ks++) {
            int arow = warp_m + (lane & 15);
            int acol = ks*16 + (lane >> 4)*8;
            uint32_t ahf[2][4], alf[2][4];
#pragma unroll
            for (int mt = 0; mt < 2; mt++) {
                uint32_t bo = (uint32_t)((arow + mt*16)*(GSTRIDE*2) + acol*2);
                ldsm4(ahf[mt], ah_b + bo);
                ldsm4(alf[mt], al_b + bo);
            }
            int brow = warp_n + (lane & 7) + ((lane >> 4) << 3);
            int bcol = ks*16 + (((lane >> 3) & 1) << 3);
#pragma unroll
            for (int np = 0; np < 3; np++) {
                uint32_t bhf[4], blf[4];
                uint32_t bo = (uint32_t)((brow + np*16)*(GSTRIDE*2) + bcol*2);
                ldsm4(bhf, bh_b + bo);
                ldsm4(blf, bl_b + bo);
#pragma unroll
                for (int half = 0; half < 2; half++) {
                    int nt = np*2 + half;
#pragma unroll
                    for (int mt = 0; mt < 2; mt++) {
                        mma_bf16(acc[mt][nt], ahf[mt], bhf[half*2], bhf[half*2+1]);
                        mma_bf16(acc[mt][nt], ahf[mt], blf[half*2], blf[half*2+1]);
                        mma_bf16(acc[mt][nt], alf[mt], bhf[half*2], bhf[half*2+1]);
                    }
                }
            }
        }
    }

    int g = lane >> 2, tig = lane & 3;
#pragma unroll
    for (int mt = 0; mt < 2; mt++) {
#pragma unroll
        for (int nt = 0; nt < 6; nt++) {
            int m0 = mb + warp_m + mt*16 + g;
            int col = nloc + warp_n + nt*8 + tig*2;
            float2 v0 = make_float2(acc[mt][nt][0], acc[mt][nt][1]);
            float2 v1 = make_float2(acc[mt][nt][2], acc[mt][nt][3]);
            if (dosig) {
                v0.x = 1.f/(1.f+__expf(-v0.x)); v0.y = 1.f/(1.f+__expf(-v0.y));
                v1.x = 1.f/(1.f+__expf(-v1.x)); v1.y = 1.f/(1.f+__expf(-v1.y));
            }
            *(float2*)&Out[(size_t)m0*CC + col]     = v0;
            *(float2*)&Out[(size_t)(m0+8)*CC + col] = v1;
        }
    }
}

__global__ __launch_bounds__(256)
void gemm_kvr_h(const float* __restrict__ Wk, const float* __restrict__ Wv,
                const float* __restrict__ Wr) {
    __shared__ __align__(16) GemmSmem S;
    int nb = blockIdx.x * 96;
    int sel = nb / CC, nloc = nb % CC;
    const float* Wsrc = (sel == 0) ? Wk : (sel == 1) ? Wv : Wr;
    float* Out        = (sel == 0) ? g_k : (sel == 1) ? g_v : g_r;
    gemm_core(false, Wsrc, Out, nloc, blockIdx.y * 128, sel == 2, S);
}

__global__ __launch_bounds__(256)
void gemm_out_h(const float* __restrict__ Wo, float* __restrict__ outp) {
    __shared__ __align__(16) GemmSmem S;
    gemm_core(true, Wo, outp, blockIdx.x * 96, blockIdx.y * 128, false, S);
}

// ---------------- 4. WKV chunked parallel scan (float2, closed-form scale) -
// pass1 stores chunk summaries pre-scaled by e^{-ci*Wc}; cscan is then a
// plain exclusive prefix-sum; pass2 reconstructs via o = 48*ci*w analytically.
__device__ __forceinline__ void chunk_map(int ci, int j, int& t0, int& stp) {
    if (j == 0) { t0 = ci * CS; stp = 1; }
    else        { t0 = ((ci & 1) * CS) * CW + (ci >> 1); stp = CW; }
}

__global__ void wkv_pass1(const float* __restrict__ sd, int j) {
    int ci = blockIdx.x, b = blockIdx.y, c2 = threadIdx.x * 2;
    float2 wv = *(const float2*)&sd[c2];
    float wlx = wv.x * (1.0f/(float)CT) * L2E;
    float wly = wv.y * (1.0f/(float)CT) * L2E;
    float Sx = 0.f, Sy = 0.f, Qx = 0.f, Qy = 0.f;
    float ofx = -wlx, ofy = -wly;
    size_t base = (size_t)b*CT*CC + c2;
    int t0, stp; chunk_map(ci, j, t0, stp);
    size_t o = base + (size_t)t0*CC;
    size_t ostep = (size_t)stp*CC;
    float2 kb[4], vb[4];
#pragma unroll
    for (int p = 0; p < 4; p++) {
        kb[p] = *(const float2*)&g_k[o + p*ostep];
        vb[p] = *(const float2*)&g_v[o + p*ostep];
    }
#pragma unroll 1
    for (int i = 0; i < CS; i += 4) {
        float2 kn[4], vn[4];
        if (i + 4 < CS) {
            size_t on = o + 4*ostep;
#pragma unroll
            for (int p = 0; p < 4; p++) {
                kn[p] = *(const float2*)&g_k[on + p*ostep];
                vn[p] = *(const float2*)&g_v[on + p*ostep];
            }
        }
#pragma unroll
        for (int p = 0; p < 4; p++) {
            float Ex = exp2f(fmaf(kb[p].x, L2E, ofx));
            float Ey = exp2f(fmaf(kb[p].y, L2E, ofy));
            Sx = fmaf(Ex, vb[p].x, Sx);
            Sy = fmaf(Ey, vb[p].y, Sy);
            Qx += Ex; Qy += Ey;
            ofx -= wlx; ofy -= wly;
        }
#pragma unroll
        for (int p = 0; p < 4; p++) { kb[p] = kn[p]; vb[p] = vn[p]; }
        o += 4*ostep;
    }
    // scale by e^{-ci*Wc} = 2^{-48*ci*w*log2e} so cscan is a plain prefix sum
    float scx = exp2f(-48.f*(float)ci*wlx);
    float scy = exp2f(-48.f*(float)ci*wly);
    int sidx = (b*NCHUNK + ci)*CC + c2;
    *(float2*)&g_sp[sidx] = make_float2(Sx*scx, Sy*scy);
    *(float2*)&g_sq[sidx] = make_float2(Qx*scx, Qy*scy);
}

// exclusive prefix-sum over 192 chunks; separate outputs (no aliasing, loads pipeline)
__global__ void wkv_cscan() {
    int b = blockIdx.x;
    int c = blockIdx.y * 32 + threadIdx.x;
    int sidx0 = b*NCHUNK*CC + c;
    float p = 0.f, q = 0.f;
    float Pb[4], Qb[4];
#pragma unroll
    for (int t = 0; t < 4; t++) { Pb[t] = g_sp[sidx0 + t*CC]; Qb[t] = g_sq[sidx0 + t*CC]; }
#pragma unroll 1
    for (int j = 0; j < NCHUNK; j += 4) {
        float Pn[4], Qn[4];
        if (j + 4 < NCHUNK) {
            int s2 = sidx0 + (j + 4)*CC;
#pragma unroll
            for (int t = 0; t < 4; t++) { Pn[t] = g_sp[s2 + t*CC]; Qn[t] = g_sq[s2 + t*CC]; }
        }
#pragma unroll
        for (int t = 0; t < 4; t++) {
            int s = sidx0 + (j + t)*CC;
            g_so[s]  = p;
            g_sq2[s] = q;
            p += Pb[t]; q += Qb[t];
        }
#pragma unroll
        for (int t = 0; t < 4; t++) { Pb[t] = Pn[t]; Qb[t] = Qn[t]; }
    }
}

__global__ void wkv_pass2(const float* __restrict__ sd, const float* __restrict__ sf,
                          int j) {
    int ci = blockIdx.x, b = blockIdx.y, c2 = threadIdx.x * 2;
    float2 wv = *(const float2*)&sd[c2];
    float2 uv = *(const float2*)&sf[c2];
    float wx = wv.x * (1.0f/(float)CT), wy = wv.y * (1.0f/(float)CT);
    float ux = uv.x * (1.0f/(float)CT), uy = uv.y * (1.0f/(float)CT);
    float wlx = wx * L2E, wly = wy * L2E;
    float c1x = exp2f(-(ux + wx)*L2E);
    float c1y = exp2f(-(uy + wy)*L2E);
    int sidx = (b*NCHUNK + ci)*CC + c2;
    float2 pv = *(float2*)&g_so[sidx];    // exclusive prefix p at scale o=48*ci*w
    float2 qv = *(float2*)&g_sq2[sidx];
    float px = pv.x, py = pv.y, qx = qv.x, qy = qv.y;
    float ofux = (ux - 48.f*(float)ci*wx)*L2E;
    float ofuy = (uy - 48.f*(float)ci*wy)*L2E;
    size_t base = (size_t)b*CT*CC + c2;
    int t0, stp; chunk_map(ci, j, t0, stp);
    size_t oc = base + (size_t)t0*CC;
    size_t ostep = (size_t)stp*CC;
    float2 kb[4], vb[4];
#pragma unroll
    for (int p = 0; p < 4; p++) {
        kb[p] = *(const float2*)&g_k[oc + p*ostep];
        vb[p] = *(const float2*)&g_v[oc + p*ostep];
    }
#pragma unroll 1
    for (int i = 0; i < CS; i += 4) {
        float2 kn[4], vn[4];
        if (i + 4 < CS) {
            size_t on = oc + 4*ostep;
#pragma unroll
            for (int p = 0; p < 4; p++) {
                kn[p] = *(const float2*)&g_k[on + p*ostep];
                vn[p] = *(const float2*)&g_v[on + p*ostep];
            }
        }
#pragma unroll
        for (int p = 0; p < 4; p++) {
            float Eux = exp2f(fmaf(kb[p].x, L2E, ofux));
            float Euy = exp2f(fmaf(kb[p].y, L2E, ofuy));
            float yx = __fdividef(fmaf(Eux, vb[p].x, px), qx + Eux);
            float yy = __fdividef(fmaf(Euy, vb[p].y, py), qy + Euy);
            *(float2*)&g_v[oc + p*ostep] = make_float2(yx, yy);
            float Ex = Eux * c1x, Ey = Euy * c1y;
            px = fmaf(Ex, vb[p].x, px);
            py = fmaf(Ey, vb[p].y, py);
            qx += Ex; qy += Ey;
            ofux -= wlx; ofuy -= wly;
        }
#pragma unroll
        for (int p = 0; p < 4; p++) { kb[p] = kn[p]; vb[p] = vn[p]; }
        oc += 4*ostep;
    }
}

// ---------------- launcher -------------------------------------------------
extern "C" void kernel_launch(void* const* d_in, const int* in_sizes, int n_in,
                              void* d_out, int out_size) {
    const float* x     = (const float*)d_in[0];
    const float* alpha = (const float*)d_in[1];
    const float* w1    = (const float*)d_in[2];
    const float* w3    = (const float*)d_in[3];
    const float* w5    = (const float*)d_in[4];
    const float* Wk    = (const float*)d_in[5];
    const float* Wv    = (const float*)d_in[6];
    const float* Wr    = (const float*)d_in[7];
    const float* Wo    = (const float*)d_in[8];
    const float* sd    = (const float*)d_in[9];
    const float* sf    = (const float*)d_in[10];
    float* out = (float*)d_out;

    conv5<<<dim3(CH/2, CB), CC>>>(x, alpha, w1, w3, w5);
    gemm_kvr_h<<<dim3(6, CM/128), 256>>>(Wk, Wv, Wr);

    // scan j = 0: row-major
    wkv_pass1<<<dim3(NCHUNK, CB), CC/2>>>(sd, 0);
    wkv_cscan<<<dim3(CB, 6), 32>>>();
    wkv_pass2<<<dim3(NCHUNK, CB), CC/2>>>(sd, sf, 0);

    // scan j = 1: column-major
    wkv_pass1<<<dim3(NCHUNK, CB), CC/2>>>(sd + CC, 1);
    wkv_cscan<<<dim3(CB, 6), 32>>>();
    wkv_pass2<<<dim3(NCHUNK, CB), CC/2>>>(sd + CC, sf + CC, 1);

    gemm_out_h<<<dim3(2, CM/128), 256>>>(Wo, out);
}

// round 16
// speedup vs baseline: 1.4786x; 1.0543x over previous
#include <cuda_runtime.h>
#include <cuda_bf16.h>
#include <cstdint>

// Problem constants (fixed by setup_inputs)
#define CB 8
#define CH 96
#define CW 96
#define CC 192
#define CT (CH*CW)          // 9216
#define CM (CB*CT)          // 73728
#define L2E 1.4426950408889634f
#define NCHUNK 192
#define CS 48               // wkv chunk size

// ---------------- scratch (static __device__; no runtime allocation) -------
__device__ __align__(16) float g_xs[CM*CC];     // omni-shift output
__device__ __align__(16) float g_k [CM*CC];
__device__ __align__(16) float g_v [CM*CC];     // v -> y1 -> y2 (in-place)
__device__ __align__(16) float g_r [CM*CC];     // sigmoid(r)
__device__ __align__(16) float g_sp [CB*NCHUNK*CC];  // scaled chunk summaries (p)
__device__ __align__(16) float g_sq [CB*NCHUNK*CC];  // scaled chunk summaries (q)
__device__ __align__(16) float g_so [CB*NCHUNK*CC];  // exclusive prefix (p)
__device__ __align__(16) float g_sq2[CB*NCHUNK*CC];  // exclusive prefix (q)

// ---------------- 2. depthwise 5x5 conv (weights combined inline) ----------
__global__ __launch_bounds__(CC) void conv5(const float* __restrict__ x,
                                            const float* __restrict__ alpha,
                                            const float* __restrict__ w1,
                                            const float* __restrict__ w3,
                                            const float* __restrict__ w5) {
    int h0 = blockIdx.x * 2, b = blockIdx.y, c = threadIdx.x;
    float a0c = alpha[0], a1c = alpha[1], a2c = alpha[2], a3c = alpha[3];
    float wr[25];
#pragma unroll
    for (int tap = 0; tap < 25; tap++) {
        int dy = tap / 5, dx = tap % 5;
        float v = a3c * w5[c*25 + tap];
        if (dy == 2 && dx == 2) v += a0c + a1c * w1[c];
        if (dy >= 1 && dy <= 3 && dx >= 1 && dx <= 3)
            v += a2c * w3[c*9 + (dy-1)*3 + (dx-1)];
        wr[tap] = v;
    }
    bool rv[6];
#pragma unroll
    for (int r = 0; r < 6; r++) rv[r] = (unsigned)(h0 - 2 + r) < CH;
    const float* xb = x    + (size_t)b*CT*CC + c;
    float*       ob = g_xs + (size_t)b*CT*CC + c;
    float win[6][5];
#pragma unroll
    for (int r = 0; r < 6; r++) {
        int hy = h0 - 2 + r;
        win[r][0] = 0.f; win[r][1] = 0.f;
        win[r][2] = rv[r] ? xb[(size_t)(hy*CW + 0)*CC] : 0.f;
        win[r][3] = rv[r] ? xb[(size_t)(hy*CW + 1)*CC] : 0.f;
        win[r][4] = 0.f;
    }
#pragma unroll 4
    for (int w = 0; w < CW; w++) {
        int wx = w + 2;
        bool cv = wx < CW;
#pragma unroll
        for (int r = 0; r < 6; r++)
            win[r][4] = (rv[r] && cv) ? xb[(size_t)((h0-2+r)*CW + wx)*CC] : 0.f;
        float a0 = 0.f, a1 = 0.f;
#pragma unroll
        for (int dy = 0; dy < 5; dy++)
#pragma unroll
            for (int j = 0; j < 5; j++) {
                a0 = fmaf(win[dy][j],   wr[dy*5+j], a0);
                a1 = fmaf(win[dy+1][j], wr[dy*5+j], a1);
            }
        ob[(size_t)(h0*CW + w)*CC]     = a0;
        ob[(size_t)((h0+1)*CW + w)*CC] = a1;
#pragma unroll
        for (int r = 0; r < 6; r++)
#pragma unroll
            for (int j = 0; j < 4; j++)
                win[r][j] = win[r][j+1];
    }
}

// ================= HMMA bf16 GEMM (R10 485us version, verbatim) ============
#define GSTRIDE 40   // smem row stride in bf16 elements (80 bytes)

__device__ __forceinline__ void split2(float a, float b, uint32_t& hi, uint32_t& lo) {
    __nv_bfloat16 ha = __float2bfloat16(a), hb = __float2bfloat16(b);
    float ra = a - __bfloat162float(ha), rb = b - __bfloat162float(hb);
    __nv_bfloat16 la = __float2bfloat16(ra), lb = __float2bfloat16(rb);
    hi = ((uint32_t)__bfloat16_as_ushort(hb) << 16) | (uint32_t)__bfloat16_as_ushort(ha);
    lo = ((uint32_t)__bfloat16_as_ushort(lb) << 16) | (uint32_t)__bfloat16_as_ushort(la);
}
__device__ __forceinline__ uint32_t smem_u32(const void* p) {
    uint32_t a;
    asm("{ .reg .u64 t; cvta.to.shared.u64 t, %1; cvt.u32.u64 %0, t; }" : "=r"(a) : "l"(p));
    return a;
}
__device__ __forceinline__ void ldsm4(uint32_t* r, uint32_t addr) {
    asm volatile("ldmatrix.sync.aligned.m8n8.x4.shared.b16 {%0,%1,%2,%3}, [%4];"
        : "=r"(r[0]), "=r"(r[1]), "=r"(r[2]), "=r"(r[3]) : "r"(addr));
}
__device__ __forceinline__ void mma_bf16(float* c, const uint32_t* a, uint32_t b0, uint32_t b1) {
    asm volatile("mma.sync.aligned.m16n8k16.row.col.f32.bf16.bf16.f32 "
        "{%0,%1,%2,%3}, {%4,%5,%6,%7}, {%8,%9}, {%0,%1,%2,%3};"
        : "+f"(c[0]), "+f"(c[1]), "+f"(c[2]), "+f"(c[3])
        : "r"(a[0]), "r"(a[1]), "r"(a[2]), "r"(a[3]), "r"(b0), "r"(b1));
}

struct GemmSmem {
    uint16_t Ah[128*GSTRIDE];
    uint16_t Al[128*GSTRIDE];
    uint16_t Bh[96*GSTRIDE];
    uint16_t Bl[96*GSTRIDE];
};

__device__ __forceinline__ void gemm_core(bool is_out, const float* __restrict__ Wsrc,
                                          float* __restrict__ Out, int nloc, int mb,
                                          bool dosig, GemmSmem& S) {
    int tid = threadIdx.x, lane = tid & 31, wid = tid >> 5;
    int warp_m = (wid & 3) * 32, warp_n = (wid >> 2) * 48;

    float acc[2][6][4];
#pragma unroll
    for (int i = 0; i < 2; i++)
#pragma unroll
        for (int j = 0; j < 6; j++)
#pragma unroll
            for (int q = 0; q < 4; q++) acc[i][j][q] = 0.f;

    int aRow[4], aKq[4], bRow[3], bKq[3];
#pragma unroll
    for (int p = 0; p < 4; p++) { int idx = tid + 256*p; aRow[p] = idx >> 3; aKq[p] = idx & 7; }
#pragma unroll
    for (int p = 0; p < 3; p++) { int idx = tid + 256*p; bRow[p] = idx >> 3; bKq[p] = idx & 7; }

    float4 pa[4], pb[3];
#pragma unroll
    for (int p = 0; p < 4; p++) {
        size_t off = (size_t)(mb + aRow[p])*CC + aKq[p]*4;
        if (!is_out) pa[p] = *(const float4*)&g_xs[off];
        else {
            float4 r = *(const float4*)&g_r[off];
            float4 v = *(const float4*)&g_v[off];
            pa[p] = make_float4(r.x*v.x, r.y*v.y, r.z*v.z, r.w*v.w);
        }
    }
#pragma unroll
    for (int p = 0; p < 3; p++)
        pb[p] = *(const float4*)&Wsrc[(size_t)(nloc + bRow[p])*CC + bKq[p]*4];

    uint32_t ah_b = smem_u32(S.Ah), al_b = smem_u32(S.Al);
    uint32_t bh_b = smem_u32(S.Bh), bl_b = smem_u32(S.Bl);

#pragma unroll 1
    for (int st = 0; st < 6; st++) {
        __syncthreads();
#pragma unroll
        for (int p = 0; p < 4; p++) {
            uint32_t h0, l0, h1, l1;
            split2(pa[p].x, pa[p].y, h0, l0);
            split2(pa[p].z, pa[p].w, h1, l1);
            int bo = aRow[p]*(GSTRIDE*2) + aKq[p]*8;
            *(uint2*)((char*)S.Ah + bo) = make_uint2(h0, h1);
            *(uint2*)((char*)S.Al + bo) = make_uint2(l0, l1);
        }
#pragma unroll
        for (int p = 0; p < 3; p++) {
            uint32_t h0, l0, h1, l1;
            split2(pb[p].x, pb[p].y, h0, l0);
            split2(pb[p].z, pb[p].w, h1, l1);
            int bo = bRow[p]*(GSTRIDE*2) + bKq[p]*8;
            *(uint2*)((char*)S.Bh + bo) = make_uint2(h0, h1);
            *(uint2*)((char*)S.Bl + bo) = make_uint2(l0, l1);
        }
        __syncthreads();
        if (st < 5) {
            int k0 = (st + 1) * 32;
#pragma unroll
            for (int p = 0; p < 4; p++) {
                size_t off = (size_t)(mb + aRow[p])*CC + k0 + aKq[p]*4;
                if (!is_out) pa[p] = *(const float4*)&g_xs[off];
                else {
                    float4 r = *(const float4*)&g_r[off];
                    float4 v = *(const float4*)&g_v[off];
                    pa[p] = make_float4(r.x*v.x, r.y*v.y, r.z*v.z, r.w*v.w);
                }
            }
#pragma unroll
            for (int p = 0; p < 3; p++)
                pb[p] = *(const float4*)&Wsrc[(size_t)(nloc + bRow[p])*CC + k0 + bKq[p]*4];
        }
#pragma unroll 1
        for (int ks = 0; ks < 2; ks++) {
            int arow = warp_m + (lane & 15);
            int acol = ks*16 + (lane >> 4)*8;
            uint32_t ahf[2][4], alf[2][4];
#pragma unroll
            for (int mt = 0; mt < 2; mt++) {
                uint32_t bo = (uint32_t)((arow + mt*16)*(GSTRIDE*2) + acol*2);
                ldsm4(ahf[mt], ah_b + bo);
                ldsm4(alf[mt], al_b + bo);
            }
            int brow = warp_n + (lane & 7) + ((lane >> 4) << 3);
            int bcol = ks*16 + (((lane >> 3) & 1) << 3);
#pragma unroll
            for (int np = 0; np < 3; np++) {
                uint32_t bhf[4], blf[4];
                uint32_t bo = (uint32_t)((brow + np*16)*(GSTRIDE*2) + bcol*2);
                ldsm4(bhf, bh_b + bo);
                ldsm4(blf, bl_b + bo);
#pragma unroll
                for (int half = 0; half < 2; half++) {
                    int nt = np*2 + half;
#pragma unroll
                    for (int mt = 0; mt < 2; mt++) {
                        mma_bf16(acc[mt][nt], ahf[mt], bhf[half*2], bhf[half*2+1]);
                        mma_bf16(acc[mt][nt], ahf[mt], blf[half*2], blf[half*2+1]);
                        mma_bf16(acc[mt][nt], alf[mt], bhf[half*2], bhf[half*2+1]);
                    }
                }
            }
        }
    }

    int g = lane >> 2, tig = lane & 3;
#pragma unroll
    for (int mt = 0; mt < 2; mt++) {
#pragma unroll
        for (int nt = 0; nt < 6; nt++) {
            int m0 = mb + warp_m + mt*16 + g;
            int col = nloc + warp_n + nt*8 + tig*2;
            float2 v0 = make_float2(acc[mt][nt][0], acc[mt][nt][1]);
            float2 v1 = make_float2(acc[mt][nt][2], acc[mt][nt][3]);
            if (dosig) {
                v0.x = 1.f/(1.f+__expf(-v0.x)); v0.y = 1.f/(1.f+__expf(-v0.y));
                v1.x = 1.f/(1.f+__expf(-v1.x)); v1.y = 1.f/(1.f+__expf(-v1.y));
            }
            *(float2*)&Out[(size_t)m0*CC + col]     = v0;
            *(float2*)&Out[(size_t)(m0+8)*CC + col] = v1;
        }
    }
}

__global__ __launch_bounds__(256)
void gemm_kvr_h(const float* __restrict__ Wk, const float* __restrict__ Wv,
                const float* __restrict__ Wr) {
    __shared__ __align__(16) GemmSmem S;
    int nb = blockIdx.x * 96;
    int sel = nb / CC, nloc = nb % CC;
    const float* Wsrc = (sel == 0) ? Wk : (sel == 1) ? Wv : Wr;
    float* Out        = (sel == 0) ? g_k : (sel == 1) ? g_v : g_r;
    gemm_core(false, Wsrc, Out, nloc, blockIdx.y * 128, sel == 2, S);
}

__global__ __launch_bounds__(256)
void gemm_out_h(const float* __restrict__ Wo, float* __restrict__ outp) {
    __shared__ __align__(16) GemmSmem S;
    gemm_core(true, Wo, outp, blockIdx.x * 96, blockIdx.y * 128, false, S);
}

// ---------------- 4. WKV chunked parallel scan (float2, closed-form scale) -
__device__ __forceinline__ void chunk_map(int ci, int j, int& t0, int& stp) {
    if (j == 0) { t0 = ci * CS; stp = 1; }
    else        { t0 = ((ci & 1) * CS) * CW + (ci >> 1); stp = CW; }
}

__global__ void wkv_pass1(const float* __restrict__ sd, int j) {
    int ci = blockIdx.x, b = blockIdx.y, c2 = threadIdx.x * 2;
    float2 wv = *(const float2*)&sd[c2];
    float wlx = wv.x * (1.0f/(float)CT) * L2E;
    float wly = wv.y * (1.0f/(float)CT) * L2E;
    float Sx = 0.f, Sy = 0.f, Qx = 0.f, Qy = 0.f;
    float ofx = -wlx, ofy = -wly;
    size_t base = (size_t)b*CT*CC + c2;
    int t0, stp; chunk_map(ci, j, t0, stp);
    size_t o = base + (size_t)t0*CC;
    size_t ostep = (size_t)stp*CC;
    float2 kb[4], vb[4];
#pragma unroll
    for (int p = 0; p < 4; p++) {
        kb[p] = *(const float2*)&g_k[o + p*ostep];
        vb[p] = *(const float2*)&g_v[o + p*ostep];
    }
#pragma unroll 1
    for (int i = 0; i < CS; i += 4) {
        float2 kn[4], vn[4];
        if (i + 4 < CS) {
            size_t on = o + 4*ostep;
#pragma unroll
            for (int p = 0; p < 4; p++) {
                kn[p] = *(const float2*)&g_k[on + p*ostep];
                vn[p] = *(const float2*)&g_v[on + p*ostep];
            }
        }
#pragma unroll
        for (int p = 0; p < 4; p++) {
            float Ex = exp2f(fmaf(kb[p].x, L2E, ofx));
            float Ey = exp2f(fmaf(kb[p].y, L2E, ofy));
            Sx = fmaf(Ex, vb[p].x, Sx);
            Sy = fmaf(Ey, vb[p].y, Sy);
            Qx += Ex; Qy += Ey;
            ofx -= wlx; ofy -= wly;
        }
#pragma unroll
        for (int p = 0; p < 4; p++) { kb[p] = kn[p]; vb[p] = vn[p]; }
        o += 4*ostep;
    }
    float scx = exp2f(-48.f*(float)ci*wlx);
    float scy = exp2f(-48.f*(float)ci*wly);
    int sidx = (b*NCHUNK + ci)*CC + c2;
    *(float2*)&g_sp[sidx] = make_float2(Sx*scx, Sy*scy);
    *(float2*)&g_sq[sidx] = make_float2(Qx*scx, Qy*scy);
}

// warp-parallel exclusive prefix scan: ONE WARP PER BLOCK, one (b,c) chain.
// lane owns 6 consecutive chunks; shfl inclusive scan combines lane totals.
__global__ __launch_bounds__(32) void wkv_cscan() {
    int c = blockIdx.x, b = blockIdx.y;
    unsigned lane = threadIdx.x;
    int sidx0 = b*NCHUNK*CC + c + (int)lane*6*CC;
    float P[6], Q[6];
#pragma unroll
    for (int t = 0; t < 6; t++) {
        P[t] = g_sp[sidx0 + t*CC];
        Q[t] = g_sq[sidx0 + t*CC];
    }
    float ex0 = P[0], eq0 = Q[0];
#pragma unroll
    for (int t = 1; t < 6; t++) { ex0 += P[t]; eq0 += Q[t]; }
    // inclusive shfl scan of per-lane totals
    float tp = ex0, tq = eq0;
#pragma unroll
    for (int ofs = 1; ofs < 32; ofs <<= 1) {
        float ap = __shfl_up_sync(0xffffffffu, tp, ofs);
        float aq = __shfl_up_sync(0xffffffffu, tq, ofs);
        if (lane >= ofs) { tp += ap; tq += aq; }
    }
    float rp = tp - ex0, rq = tq - eq0;   // exclusive base for this lane
#pragma unroll
    for (int t = 0; t < 6; t++) {
        g_so [sidx0 + t*CC] = rp;
        g_sq2[sidx0 + t*CC] = rq;
        rp += P[t]; rq += Q[t];
    }
}

__global__ void wkv_pass2(const float* __restrict__ sd, const float* __restrict__ sf,
                          int j) {
    int ci = blockIdx.x, b = blockIdx.y, c2 = threadIdx.x * 2;
    float2 wv = *(const float2*)&sd[c2];
    float2 uv = *(const float2*)&sf[c2];
    float wx = wv.x * (1.0f/(float)CT), wy = wv.y * (1.0f/(float)CT);
    float ux = uv.x * (1.0f/(float)CT), uy = uv.y * (1.0f/(float)CT);
    float wlx = wx * L2E, wly = wy * L2E;
    float c1x = exp2f(-(ux + wx)*L2E);
    float c1y = exp2f(-(uy + wy)*L2E);
    int sidx = (b*NCHUNK + ci)*CC + c2;
    float2 pv = *(float2*)&g_so[sidx];
    float2 qv = *(float2*)&g_sq2[sidx];
    float px = pv.x, py = pv.y, qx = qv.x, qy = qv.y;
    float ofux = (ux - 48.f*(float)ci*wx)*L2E;
    float ofuy = (uy - 48.f*(float)ci*wy)*L2E;
    size_t base = (size_t)b*CT*CC + c2;
    int t0, stp; chunk_map(ci, j, t0, stp);
    size_t oc = base + (size_t)t0*CC;
    size_t ostep = (size_t)stp*CC;
    float2 kb[4], vb[4];
#pragma unroll
    for (int p = 0; p < 4; p++) {
        kb[p] = *(const float2*)&g_k[oc + p*ostep];
        vb[p] = *(const float2*)&g_v[oc + p*ostep];
    }
#pragma unroll 1
    for (int i = 0; i < CS; i += 4) {
        float2 kn[4], vn[4];
        if (i + 4 < CS) {
            size_t on = oc + 4*ostep;
#pragma unroll
            for (int p = 0; p < 4; p++) {
                kn[p] = *(const float2*)&g_k[on + p*ostep];
                vn[p] = *(const float2*)&g_v[on + p*ostep];
            }
        }
#pragma unroll
        for (int p = 0; p < 4; p++) {
            float Eux = exp2f(fmaf(kb[p].x, L2E, ofux));
            float Euy = exp2f(fmaf(kb[p].y, L2E, ofuy));
            float yx = __fdividef(fmaf(Eux, vb[p].x, px), qx + Eux);
            float yy = __fdividef(fmaf(Euy, vb[p].y, py), qy + Euy);
            *(float2*)&g_v[oc + p*ostep] = make_float2(yx, yy);
            float Ex = Eux * c1x, Ey = Euy * c1y;
            px = fmaf(Ex, vb[p].x, px);
            py = fmaf(Ey, vb[p].y, py);
            qx += Ex; qy += Ey;
            ofux -= wlx; ofuy -= wly;
        }
#pragma unroll
        for (int p = 0; p < 4; p++) { kb[p] = kn[p]; vb[p] = vn[p]; }
        oc += 4*ostep;
    }
}

// ---------------- launcher -------------------------------------------------
extern "C" void kernel_launch(void* const* d_in, const int* in_sizes, int n_in,
                              void* d_out, int out_size) {
    const float* x     = (const float*)d_in[0];
    const float* alpha = (const float*)d_in[1];
    const float* w1    = (const float*)d_in[2];
    const float* w3    = (const float*)d_in[3];
    const float* w5    = (const float*)d_in[4];
    const float* Wk    = (const float*)d_in[5];
    const float* Wv    = (const float*)d_in[6];
    const float* Wr    = (const float*)d_in[7];
    const float* Wo    = (const float*)d_in[8];
    const float* sd    = (const float*)d_in[9];
    const float* sf    = (const float*)d_in[10];
    float* out = (float*)d_out;

    conv5<<<dim3(CH/2, CB), CC>>>(x, alpha, w1, w3, w5);
    gemm_kvr_h<<<dim3(6, CM/128), 256>>>(Wk, Wv, Wr);

    // scan j = 0: row-major
    wkv_pass1<<<dim3(NCHUNK, CB), CC/2>>>(sd, 0);
    wkv_cscan<<<dim3(CC, CB), 32>>>();
    wkv_pass2<<<dim3(NCHUNK, CB), CC/2>>>(sd, sf, 0);

    // scan j = 1: column-major
    wkv_pass1<<<dim3(NCHUNK, CB), CC/2>>>(sd + CC, 1);
    wkv_cscan<<<dim3(CC, CB), 32>>>();
    wkv_pass2<<<dim3(NCHUNK, CB), CC/2>>>(sd + CC, sf + CC, 1);

    gemm_out_h<<<dim3(2, CM/128), 256>>>(Wo, out);
}